// round 3
// baseline (speedup 1.0000x reference)
#include <cuda_runtime.h>

// Problem constants (shapes fixed by setup_inputs)
#define BATCH 256
#define UNITS 1024
#define FEATS 16
#define WCOLS 4096          // 4*UNITS
#define OUTSTEPS 24
#define LEAKF 0.001f
#define MASKV (-1.0f)

// -------- device scratch (no allocation allowed) --------
__device__ float g_h[2][BATCH * UNITS];
__device__ float g_c[2][BATCH * UNITS];
__device__ float g_p[BATCH * FEATS];
__device__ float g_d1[BATCH * 256];
__device__ float g_d2[BATCH * 128];
__device__ float g_d3[BATCH * 64];
__device__ float g_Wr[UNITS * WCOLS];   // gate-interleaved rec_kernel: Wr[k][4u+g]
__device__ float g_Kr[FEATS * WCOLS];   // gate-interleaved input kernel
__device__ float g_br[WCOLS];           // gate-interleaved bias

typedef unsigned long long ull;

// packed f32x2 FMA (Blackwell FFMA2 — only reachable via PTX)
__device__ __forceinline__ void fma2(ull &acc, ull a, ull b) {
    asm("fma.rn.f32x2 %0, %1, %2, %0;" : "+l"(acc) : "l"(a), "l"(b));
}
__device__ __forceinline__ ull pack2(float x, float y) {
    ull r; asm("mov.b64 %0, {%1,%2};" : "=l"(r) : "f"(x), "f"(y)); return r;
}
__device__ __forceinline__ float2 unpk(ull v) {
    float2 r; asm("mov.b64 {%0,%1}, %2;" : "=f"(r.x), "=f"(r.y) : "l"(v)); return r;
}

// -------- init: zero h/c state --------
__global__ void init_state() {
    int i = blockIdx.x * blockDim.x + threadIdx.x;
    if (i < BATCH * UNITS) {
        g_h[0][i] = 0.f; g_h[1][i] = 0.f;
        g_c[0][i] = 0.f; g_c[1][i] = 0.f;
    }
}

// -------- reorder weights to gate-interleaved layout --------
// original column j = g*UNITS + u  ->  new column 4u + g
__global__ void reorder_weights(const float* __restrict__ rec,
                                const float* __restrict__ ker,
                                const float* __restrict__ bias) {
    for (int i = blockIdx.x * blockDim.x + threadIdx.x;
         i < UNITS * WCOLS; i += gridDim.x * blockDim.x) {
        int k = i / WCOLS;
        int j = i - k * WCOLS;
        int u = j >> 2;
        int g = j & 3;
        g_Wr[i] = rec[k * WCOLS + g * UNITS + u];
        if (k < FEATS) g_Kr[i] = ker[k * WCOLS + g * UNITS + u];
        if (k == 0)    g_br[j] = bias[g * UNITS + u];
    }
}

// -------- fused PLSTM step --------
// z = h@Wr + x@Kr + b  (gate-interleaved), then gates + time-gate + mask,
// writing h/c into the opposite parity buffer.
// Tile: 64 rows (batch) x 64 cols (16 units * 4 gates). 128 threads,
// each thread: 4 rows x 8 cols (= 2 units, all gates) via 16 f32x2 accumulators.
__global__ void __launch_bounds__(128)
step_kernel(const float* __restrict__ xbase, int xstride,
            const float* __restrict__ hin, const float* __restrict__ cin,
            float* __restrict__ hout, float* __restrict__ cout,
            const float* __restrict__ period, const float* __restrict__ phase,
            const float* __restrict__ ratio, int masked)
{
    __shared__ float2 As2[64 * 17];   // A values duplicated {a,a}; stride 17 avoids STS conflicts
    __shared__ float  Bs[16 * 64];
    __shared__ float  t_s[64];
    __shared__ int    m_s[64];

    const int tid = threadIdx.x;
    const int tx  = tid & 7;     // column group: 8 cols = 2 units
    const int ty  = tid >> 3;    // row group: 4 rows
    const int b0  = blockIdx.x * 64;
    const int n0  = blockIdx.y * 64;

    ull acc[4][4];
    {   // init accumulators with bias (same for all rows)
        const float4* bp = (const float4*)(g_br + n0 + tx * 8);
        float4 v0 = bp[0], v1 = bp[1];
        ull p0 = pack2(v0.x, v0.y), p1 = pack2(v0.z, v0.w);
        ull p2 = pack2(v1.x, v1.y), p3 = pack2(v1.z, v1.w);
        #pragma unroll
        for (int i = 0; i < 4; i++) { acc[i][0]=p0; acc[i][1]=p1; acc[i][2]=p2; acc[i][3]=p3; }
    }

    const int akk = tid & 15, ar0 = tid >> 4;   // A-tile load mapping
    const int bn  = tid & 63, bk0 = tid >> 6;   // B-tile load mapping

    // ---- main K loop over recurrent part (K=1024) ----
    for (int k0 = 0; k0 < UNITS; k0 += 16) {
        #pragma unroll
        for (int it = 0; it < 8; it++) {
            int r = ar0 + it * 8;
            float v = hin[(b0 + r) * UNITS + k0 + akk];
            As2[r * 17 + akk] = make_float2(v, v);
        }
        #pragma unroll
        for (int it = 0; it < 8; it++) {
            int kk = bk0 + it * 2;
            Bs[kk * 64 + bn] = g_Wr[(k0 + kk) * WCOLS + n0 + bn];
        }
        __syncthreads();
        #pragma unroll
        for (int kk = 0; kk < 16; kk++) {
            ull a0 = *(const ull*)&As2[(ty * 4 + 0) * 17 + kk];
            ull a1 = *(const ull*)&As2[(ty * 4 + 1) * 17 + kk];
            ull a2 = *(const ull*)&As2[(ty * 4 + 2) * 17 + kk];
            ull a3 = *(const ull*)&As2[(ty * 4 + 3) * 17 + kk];
            const ulonglong2* bp = (const ulonglong2*)&Bs[kk * 64 + tx * 8];
            ulonglong2 bA = bp[0], bB = bp[1];
            fma2(acc[0][0], a0, bA.x); fma2(acc[0][1], a0, bA.y);
            fma2(acc[0][2], a0, bB.x); fma2(acc[0][3], a0, bB.y);
            fma2(acc[1][0], a1, bA.x); fma2(acc[1][1], a1, bA.y);
            fma2(acc[1][2], a1, bB.x); fma2(acc[1][3], a1, bB.y);
            fma2(acc[2][0], a2, bA.x); fma2(acc[2][1], a2, bA.y);
            fma2(acc[2][2], a2, bB.x); fma2(acc[2][3], a2, bB.y);
            fma2(acc[3][0], a3, bA.x); fma2(acc[3][1], a3, bA.y);
            fma2(acc[3][2], a3, bB.x); fma2(acc[3][3], a3, bB.y);
        }
        __syncthreads();
    }

    // ---- x contribution (K=16) ----
    #pragma unroll
    for (int it = 0; it < 8; it++) {
        int r = ar0 + it * 8;
        float v = xbase[(b0 + r) * xstride + akk];
        As2[r * 17 + akk] = make_float2(v, v);
    }
    #pragma unroll
    for (int it = 0; it < 8; it++) {
        int kk = bk0 + it * 2;
        Bs[kk * 64 + bn] = g_Kr[kk * WCOLS + n0 + bn];
    }
    __syncthreads();
    #pragma unroll
    for (int kk = 0; kk < 16; kk++) {
        ull a0 = *(const ull*)&As2[(ty * 4 + 0) * 17 + kk];
        ull a1 = *(const ull*)&As2[(ty * 4 + 1) * 17 + kk];
        ull a2 = *(const ull*)&As2[(ty * 4 + 2) * 17 + kk];
        ull a3 = *(const ull*)&As2[(ty * 4 + 3) * 17 + kk];
        const ulonglong2* bp = (const ulonglong2*)&Bs[kk * 64 + tx * 8];
        ulonglong2 bA = bp[0], bB = bp[1];
        fma2(acc[0][0], a0, bA.x); fma2(acc[0][1], a0, bA.y);
        fma2(acc[0][2], a0, bB.x); fma2(acc[0][3], a0, bB.y);
        fma2(acc[1][0], a1, bA.x); fma2(acc[1][1], a1, bA.y);
        fma2(acc[1][2], a1, bB.x); fma2(acc[1][3], a1, bB.y);
        fma2(acc[2][0], a2, bA.x); fma2(acc[2][1], a2, bA.y);
        fma2(acc[2][2], a2, bB.x); fma2(acc[2][3], a2, bB.y);
        fma2(acc[3][0], a3, bA.x); fma2(acc[3][1], a3, bA.y);
        fma2(acc[3][2], a3, bB.x); fma2(acc[3][3], a3, bB.y);
    }

    // mask + time value per row (feature values sit duplicated in As2)
    if (tid < 64) {
        float tval = As2[tid * 17 + 0].x;
        int m = 0;
        #pragma unroll
        for (int f = 0; f < FEATS; f++)
            if (As2[tid * 17 + f].x != MASKV) m = 1;
        t_s[tid] = tval;
        m_s[tid] = m;
    }
    __syncthreads();

    // ---- epilogue: gates + phased time-gate ----
    const int ubase = (n0 >> 2) + tx * 2;
    float per_[2], pha_[2], ro_[2];
    #pragma unroll
    for (int j = 0; j < 2; j++) {
        per_[j] = period[ubase + j];
        pha_[j] = phase[ubase + j];
        ro_[j]  = ratio[ubase + j];
    }
    #pragma unroll
    for (int i = 0; i < 4; i++) {
        int   b  = b0 + ty * 4 + i;
        float t  = t_s[ty * 4 + i];
        int   m  = m_s[ty * 4 + i];
        #pragma unroll
        for (int j = 0; j < 2; j++) {
            float2 zif = unpk(acc[i][2 * j]);      // (i, f) gates
            float2 zgo = unpk(acc[i][2 * j + 1]);  // (g, o) gates
            int u = ubase + j;
            int idx = b * UNITS + u;
            float ig = 1.f / (1.f + expf(-zif.x));
            float fg = 1.f / (1.f + expf(-zif.y));
            float gg = tanhf(zgo.x);
            float og = 1.f / (1.f + expf(-zgo.y));
            float ho = hin[idx], co = cin[idx];
            float nc = fg * co + ig * gg;
            float nh = og * tanhf(nc);
            // phased gate
            float cr = fmodf(t - pha_[j], per_[j]);
            if (cr < 0.f) cr += per_[j];
            cr = cr / per_[j];
            float kg;
            if (cr < 0.5f * ro_[j])      kg = 2.f * cr / ro_[j];
            else if (cr < ro_[j])        kg = 2.f - 2.f * cr / ro_[j];
            else                         kg = LEAKF * cr;
            float h2 = kg * nh + (1.f - kg) * ho;
            float c2 = kg * nc + (1.f - kg) * co;
            if (masked && !m) { h2 = ho; c2 = co; }
            hout[idx] = h2;
            cout[idx] = c2;
        }
    }
}

// -------- generic small dense layer: out = act(A[256,K] @ W[K,N] + b) --------
// grid (M/16, N/16), block (16,16). K and N are multiples of 16 here.
__global__ void __launch_bounds__(256)
dense_kernel(const float* __restrict__ A, int K,
             const float* __restrict__ W, int N,
             const float* __restrict__ bias,
             float* __restrict__ out, int act,
             float* __restrict__ out2, int out2_stride)
{
    __shared__ float As[16][16];
    __shared__ float Ws[16][16];
    int tx = threadIdx.x, ty = threadIdx.y;
    int m0 = blockIdx.x * 16, n0 = blockIdx.y * 16;
    float acc = 0.f;
    for (int k0 = 0; k0 < K; k0 += 16) {
        As[ty][tx] = A[(m0 + ty) * K + k0 + tx];
        Ws[ty][tx] = W[(k0 + ty) * N + n0 + tx];
        __syncthreads();
        #pragma unroll
        for (int kk = 0; kk < 16; kk++)
            acc += As[ty][kk] * Ws[kk][tx];
        __syncthreads();
    }
    int n = n0 + tx, mrow = m0 + ty;
    acc += bias[n];
    if (act) acc = tanhf(acc);
    out[mrow * N + n] = acc;
    if (out2) out2[mrow * out2_stride + n] = acc;
}

extern "C" void kernel_launch(void* const* d_in, const int* in_sizes, int n_in,
                              void* d_out, int out_size) {
    const float* x      = (const float*)d_in[0];
    const float* kernel = (const float*)d_in[1];
    const float* rec    = (const float*)d_in[2];
    const float* bias   = (const float*)d_in[3];
    const float* period = (const float*)d_in[4];
    const float* phase  = (const float*)d_in[5];
    const float* ratio  = (const float*)d_in[6];
    const float* w1 = (const float*)d_in[7];  const float* b1 = (const float*)d_in[8];
    const float* w2 = (const float*)d_in[9];  const float* b2 = (const float*)d_in[10];
    const float* w3 = (const float*)d_in[11]; const float* b3 = (const float*)d_in[12];
    const float* wo = (const float*)d_in[13]; const float* bo = (const float*)d_in[14];
    float* out = (float*)d_out;

    const int T = in_sizes[0] / (BATCH * FEATS);   // 512

    float *hb, *cb, *pb, *d1, *d2, *d3;
    cudaGetSymbolAddress((void**)&hb, g_h);
    cudaGetSymbolAddress((void**)&cb, g_c);
    cudaGetSymbolAddress((void**)&pb, g_p);
    cudaGetSymbolAddress((void**)&d1, g_d1);
    cudaGetSymbolAddress((void**)&d2, g_d2);
    cudaGetSymbolAddress((void**)&d3, g_d3);

    init_state<<<(BATCH * UNITS + 255) / 256, 256>>>();
    reorder_weights<<<4096, 256>>>(rec, kernel, bias);

    const dim3 sgrid(BATCH / 64, WCOLS / 64);   // (4, 64)
    int par = 0;

    // warm phase: 512 masked steps over x
    for (int t = 0; t < T; t++) {
        step_kernel<<<sgrid, 128>>>(x + t * FEATS, T * FEATS,
                                    hb + par * BATCH * UNITS, cb + par * BATCH * UNITS,
                                    hb + (par ^ 1) * BATCH * UNITS, cb + (par ^ 1) * BATCH * UNITS,
                                    period, phase, ratio, 1);
        par ^= 1;
    }

    // dense stack helper: h -> d1 -> d2 -> d3 -> (p, out[:,s,:])
    auto dense_stack = [&](int s) {
        const float* h = hb + par * BATCH * UNITS;
        dense_kernel<<<dim3(16,16), dim3(16,16)>>>(h,  UNITS, w1, 256, b1, d1, 1, nullptr, 0);
        dense_kernel<<<dim3(16, 8), dim3(16,16)>>>(d1, 256,   w2, 128, b2, d2, 1, nullptr, 0);
        dense_kernel<<<dim3(16, 4), dim3(16,16)>>>(d2, 128,   w3, 64,  b3, d3, 1, nullptr, 0);
        dense_kernel<<<dim3(16, 1), dim3(16,16)>>>(d3, 64,    wo, FEATS, bo, pb, 0,
                                                   out + s * FEATS, OUTSTEPS * FEATS);
    };

    dense_stack(0);   // pred0

    // autoregressive phase: 23 unmasked steps fed by p
    for (int s = 1; s < OUTSTEPS; s++) {
        step_kernel<<<sgrid, 128>>>(pb, FEATS,
                                    hb + par * BATCH * UNITS, cb + par * BATCH * UNITS,
                                    hb + (par ^ 1) * BATCH * UNITS, cb + (par ^ 1) * BATCH * UNITS,
                                    period, phase, ratio, 0);
        par ^= 1;
        dense_stack(s);
    }
}

// round 7
// speedup vs baseline: 1.1360x; 1.1360x over previous
#include <cuda_runtime.h>

// Problem constants (shapes fixed by setup_inputs)
#define BATCH 256
#define UNITS 1024
#define FEATS 16
#define WCOLS 4096          // 4*UNITS
#define OUTSTEPS 24
#define LEAKF 0.001f
#define MASKV (-1.0f)

// -------- device scratch (no allocation allowed) --------
__device__ float g_h[2][BATCH * UNITS];
__device__ float g_c[2][BATCH * UNITS];
__device__ float g_p[BATCH * FEATS];
__device__ float g_d1[BATCH * 256];
__device__ float g_d2[BATCH * 128];
__device__ float g_d3[BATCH * 64];
__device__ float g_Wr[UNITS * WCOLS];   // gate-interleaved rec_kernel: Wr[k][4u+g]
__device__ float g_Kr[FEATS * WCOLS];   // gate-interleaved input kernel
__device__ float g_br[WCOLS];           // gate-interleaved bias

typedef unsigned long long ull;

// packed f32x2 FMA (Blackwell FFMA2 — only reachable via PTX)
__device__ __forceinline__ void fma2(ull &acc, ull a, ull b) {
    asm("fma.rn.f32x2 %0, %1, %2, %0;" : "+l"(acc) : "l"(a), "l"(b));
}
__device__ __forceinline__ ull pack2(float x, float y) {
    ull r; asm("mov.b64 %0, {%1,%2};" : "=l"(r) : "f"(x), "f"(y)); return r;
}
__device__ __forceinline__ float2 unpk(ull v) {
    float2 r; asm("mov.b64 {%0,%1}, %2;" : "=f"(r.x), "=f"(r.y) : "l"(v)); return r;
}

// -------- init: zero h/c state --------
__global__ void init_state() {
    int i = blockIdx.x * blockDim.x + threadIdx.x;
    if (i < BATCH * UNITS) {
        g_h[0][i] = 0.f; g_h[1][i] = 0.f;
        g_c[0][i] = 0.f; g_c[1][i] = 0.f;
    }
}

// -------- reorder weights to gate-interleaved layout --------
// original column j = g*UNITS + u  ->  new column 4u + g
__global__ void reorder_weights(const float* __restrict__ rec,
                                const float* __restrict__ ker,
                                const float* __restrict__ bias) {
    for (int i = blockIdx.x * blockDim.x + threadIdx.x;
         i < UNITS * WCOLS; i += gridDim.x * blockDim.x) {
        int k = i / WCOLS;
        int j = i - k * WCOLS;
        int u = j >> 2;
        int g = j & 3;
        g_Wr[i] = rec[k * WCOLS + g * UNITS + u];
        if (k < FEATS) g_Kr[i] = ker[k * WCOLS + g * UNITS + u];
        if (k == 0)    g_br[j] = bias[g * UNITS + u];
    }
}

// -------- fused PLSTM step --------
// Tile: 64 rows (batch) x 64 cols (16 units * 4 gates). 64 threads (2 warps),
// each thread: 8 rows x 8 cols (= 2 units, all gates) via 32 f32x2 accumulators.
// Double-buffered smem with register prefetch: LDG(next) -> compute(cur) ->
// STS(next) -> barrier. One __syncthreads per 16-k stage.
__global__ void __launch_bounds__(64)
step_kernel(const float* __restrict__ xbase, int xstride,
            const float* __restrict__ hin, const float* __restrict__ cin,
            float* __restrict__ hout, float* __restrict__ cout,
            const float* __restrict__ period, const float* __restrict__ phase,
            const float* __restrict__ ratio, int masked)
{
    __shared__ __align__(16) float2 As2[2][64 * 17];  // [buf][row*17 + kk], {a,a} dup
    __shared__ __align__(16) float  Bs[2][16 * 64];   // [buf][kk*64 + col]
    __shared__ float t_s[64];
    __shared__ int   m_s[64];

    const int tid = threadIdx.x;
    const int tx  = tid & 7;     // column group: 8 cols = 2 units
    const int ty  = tid >> 3;    // row group: 8 rows
    const int b0  = blockIdx.x * 64;
    const int n0  = blockIdx.y * 64;

    ull acc[8][4];
    {   // init accumulators with bias (same for all rows)
        const float4* bp = (const float4*)(g_br + n0 + tx * 8);
        float4 v0 = bp[0], v1 = bp[1];
        ull p0 = pack2(v0.x, v0.y), p1 = pack2(v0.z, v0.w);
        ull p2 = pack2(v1.x, v1.y), p3 = pack2(v1.z, v1.w);
        #pragma unroll
        for (int i = 0; i < 8; i++) { acc[i][0]=p0; acc[i][1]=p1; acc[i][2]=p2; acc[i][3]=p3; }
    }

    const int bkk = tid >> 4;         // 0..3  (B-tile kk base)
    const int bc4 = (tid & 15) * 4;   // B-tile column*4

    float4 rA[4], rB[4];

    // stage s (s<64: recurrent K chunk; s==64: x-features chunk) -> registers
    auto loadStage = [&](int s) {
        if (s < 64) {
            const float* ap = hin + (b0 + tid) * UNITS + s * 16;
            #pragma unroll
            for (int q = 0; q < 4; q++) rA[q] = *(const float4*)(ap + q * 4);
            #pragma unroll
            for (int q = 0; q < 4; q++)
                rB[q] = *(const float4*)(g_Wr + (s * 16 + bkk + q * 4) * WCOLS + n0 + bc4);
        } else {
            const float* ap = xbase + (b0 + tid) * xstride;
            #pragma unroll
            for (int q = 0; q < 4; q++) rA[q] = *(const float4*)(ap + q * 4);
            #pragma unroll
            for (int q = 0; q < 4; q++)
                rB[q] = *(const float4*)(g_Kr + (bkk + q * 4) * WCOLS + n0 + bc4);
        }
    };
    // registers -> smem buffer p
    auto stsStage = [&](int p) {
        #pragma unroll
        for (int q = 0; q < 4; q++) {
            As2[p][tid * 17 + q * 4 + 0] = make_float2(rA[q].x, rA[q].x);
            As2[p][tid * 17 + q * 4 + 1] = make_float2(rA[q].y, rA[q].y);
            As2[p][tid * 17 + q * 4 + 2] = make_float2(rA[q].z, rA[q].z);
            As2[p][tid * 17 + q * 4 + 3] = make_float2(rA[q].w, rA[q].w);
            *(float4*)&Bs[p][(bkk + q * 4) * 64 + bc4] = rB[q];
        }
    };
    auto compute = [&](int p) {
        #pragma unroll
        for (int kk = 0; kk < 16; kk++) {
            ull a[8];
            #pragma unroll
            for (int i = 0; i < 8; i++)
                a[i] = *(const ull*)&As2[p][(ty * 8 + i) * 17 + kk];
            const ulonglong2* bp2 = (const ulonglong2*)&Bs[p][kk * 64 + tx * 8];
            ulonglong2 bA = bp2[0], bB = bp2[1];
            #pragma unroll
            for (int i = 0; i < 8; i++) {
                fma2(acc[i][0], a[i], bA.x);
                fma2(acc[i][1], a[i], bA.y);
                fma2(acc[i][2], a[i], bB.x);
                fma2(acc[i][3], a[i], bB.y);
            }
        }
    };

    // ---- pipelined main loop: 64 recurrent stages + 1 x stage ----
    loadStage(0);
    stsStage(0);
    __syncthreads();
    #pragma unroll 1
    for (int s = 0; s < 65; s++) {
        if (s + 1 < 65) loadStage(s + 1);
        compute(s & 1);
        if (s + 1 < 65) stsStage((s + 1) & 1);
        __syncthreads();
    }
    // stage 64 (x features) lives in buffer 0 — extract t and mask per row
    {
        float tv = As2[0][tid * 17 + 0].x;
        int m = 0;
        #pragma unroll
        for (int f = 0; f < FEATS; f++)
            if (As2[0][tid * 17 + f].x != MASKV) m = 1;
        t_s[tid] = tv;
        m_s[tid] = m;
    }
    __syncthreads();

    // ---- epilogue: gates + phased time-gate ----
    const int ubase = (n0 >> 2) + tx * 2;
    float per_[2], pha_[2], ro_[2];
    #pragma unroll
    for (int j = 0; j < 2; j++) {
        per_[j] = period[ubase + j];
        pha_[j] = phase[ubase + j];
        ro_[j]  = ratio[ubase + j];
    }
    #pragma unroll
    for (int i = 0; i < 8; i++) {
        int   b = b0 + ty * 8 + i;
        float t = t_s[ty * 8 + i];
        int   m = m_s[ty * 8 + i];
        #pragma unroll
        for (int j = 0; j < 2; j++) {
            float2 zif = unpk(acc[i][2 * j]);      // (i, f) gates
            float2 zgo = unpk(acc[i][2 * j + 1]);  // (g, o) gates
            int u = ubase + j;
            int idx = b * UNITS + u;
            float ig = 1.f / (1.f + expf(-zif.x));
            float fg = 1.f / (1.f + expf(-zif.y));
            float gg = tanhf(zgo.x);
            float og = 1.f / (1.f + expf(-zgo.y));
            float ho = hin[idx], co = cin[idx];
            float nc = fg * co + ig * gg;
            float nh = og * tanhf(nc);
            // phased gate
            float cr = fmodf(t - pha_[j], per_[j]);
            if (cr < 0.f) cr += per_[j];
            cr = cr / per_[j];
            float kg;
            if (cr < 0.5f * ro_[j])      kg = 2.f * cr / ro_[j];
            else if (cr < ro_[j])        kg = 2.f - 2.f * cr / ro_[j];
            else                         kg = LEAKF * cr;
            float h2 = kg * nh + (1.f - kg) * ho;
            float c2 = kg * nc + (1.f - kg) * co;
            if (masked && !m) { h2 = ho; c2 = co; }
            hout[idx] = h2;
            cout[idx] = c2;
        }
    }
}

// -------- generic small dense layer: out = act(A[256,K] @ W[K,N] + b) --------
// grid (M/16, N/16), block (16,16). K and N are multiples of 16 here.
__global__ void __launch_bounds__(256)
dense_kernel(const float* __restrict__ A, int K,
             const float* __restrict__ W, int N,
             const float* __restrict__ bias,
             float* __restrict__ out, int act,
             float* __restrict__ out2, int out2_stride)
{
    __shared__ float As[16][16];
    __shared__ float Ws[16][16];
    int tx = threadIdx.x, ty = threadIdx.y;
    int m0 = blockIdx.x * 16, n0 = blockIdx.y * 16;
    float acc = 0.f;
    for (int k0 = 0; k0 < K; k0 += 16) {
        As[ty][tx] = A[(m0 + ty) * K + k0 + tx];
        Ws[ty][tx] = W[(k0 + ty) * N + n0 + tx];
        __syncthreads();
        #pragma unroll
        for (int kk = 0; kk < 16; kk++)
            acc += As[ty][kk] * Ws[kk][tx];
        __syncthreads();
    }
    int n = n0 + tx, mrow = m0 + ty;
    acc += bias[n];
    if (act) acc = tanhf(acc);
    out[mrow * N + n] = acc;
    if (out2) out2[mrow * out2_stride + n] = acc;
}

extern "C" void kernel_launch(void* const* d_in, const int* in_sizes, int n_in,
                              void* d_out, int out_size) {
    const float* x      = (const float*)d_in[0];
    const float* kernel = (const float*)d_in[1];
    const float* rec    = (const float*)d_in[2];
    const float* bias   = (const float*)d_in[3];
    const float* period = (const float*)d_in[4];
    const float* phase  = (const float*)d_in[5];
    const float* ratio  = (const float*)d_in[6];
    const float* w1 = (const float*)d_in[7];  const float* b1 = (const float*)d_in[8];
    const float* w2 = (const float*)d_in[9];  const float* b2 = (const float*)d_in[10];
    const float* w3 = (const float*)d_in[11]; const float* b3 = (const float*)d_in[12];
    const float* wo = (const float*)d_in[13]; const float* bo = (const float*)d_in[14];
    float* out = (float*)d_out;

    const int T = in_sizes[0] / (BATCH * FEATS);   // 512

    float *hb, *cb, *pb, *d1, *d2, *d3;
    cudaGetSymbolAddress((void**)&hb, g_h);
    cudaGetSymbolAddress((void**)&cb, g_c);
    cudaGetSymbolAddress((void**)&pb, g_p);
    cudaGetSymbolAddress((void**)&d1, g_d1);
    cudaGetSymbolAddress((void**)&d2, g_d2);
    cudaGetSymbolAddress((void**)&d3, g_d3);

    init_state<<<(BATCH * UNITS + 255) / 256, 256>>>();
    reorder_weights<<<4096, 256>>>(rec, kernel, bias);

    const dim3 sgrid(BATCH / 64, WCOLS / 64);   // (4, 64)
    int par = 0;

    // warm phase: 512 masked steps over x
    for (int t = 0; t < T; t++) {
        step_kernel<<<sgrid, 64>>>(x + t * FEATS, T * FEATS,
                                   hb + par * BATCH * UNITS, cb + par * BATCH * UNITS,
                                   hb + (par ^ 1) * BATCH * UNITS, cb + (par ^ 1) * BATCH * UNITS,
                                   period, phase, ratio, 1);
        par ^= 1;
    }

    // dense stack helper: h -> d1 -> d2 -> d3 -> (p, out[:,s,:])
    auto dense_stack = [&](int s) {
        const float* h = hb + par * BATCH * UNITS;
        dense_kernel<<<dim3(16,16), dim3(16,16)>>>(h,  UNITS, w1, 256, b1, d1, 1, nullptr, 0);
        dense_kernel<<<dim3(16, 8), dim3(16,16)>>>(d1, 256,   w2, 128, b2, d2, 1, nullptr, 0);
        dense_kernel<<<dim3(16, 4), dim3(16,16)>>>(d2, 128,   w3, 64,  b3, d3, 1, nullptr, 0);
        dense_kernel<<<dim3(16, 1), dim3(16,16)>>>(d3, 64,    wo, FEATS, bo, pb, 0,
                                                   out + s * FEATS, OUTSTEPS * FEATS);
    };

    dense_stack(0);   // pred0

    // autoregressive phase: 23 unmasked steps fed by p
    for (int s = 1; s < OUTSTEPS; s++) {
        step_kernel<<<sgrid, 64>>>(pb, FEATS,
                                   hb + par * BATCH * UNITS, cb + par * BATCH * UNITS,
                                   hb + (par ^ 1) * BATCH * UNITS, cb + (par ^ 1) * BATCH * UNITS,
                                   period, phase, ratio, 0);
        par ^= 1;
        dense_stack(s);
    }
}

// round 9
// speedup vs baseline: 3.2657x; 2.8746x over previous
#include <cuda_runtime.h>
#include <cuda_bf16.h>
#include <cstdint>

// Problem constants (shapes fixed by setup_inputs)
#define BATCH 256
#define UNITS 1024
#define FEATS 16
#define WCOLS 4096          // 4*UNITS
#define OUTSTEPS 24
#define LEAKF 0.001f
#define MASKV (-1.0f)
#define TSTEPS 512
#define KPAD 1088           // 1024 (h) + 64 (x chunk, zero-padded past 16)
#define CHUNKS 17           // K-chunks of 64
#define BUFBYTES 49152      // Ah 8K + Al 8K + Bh 16K + Bl 16K per stage

typedef unsigned int u32;
typedef unsigned long long u64;

// -------- device scratch (no allocation allowed) --------
__device__ __align__(256) float g_h[2][BATCH * UNITS];
__device__ __align__(256) float g_c[2][BATCH * UNITS];
__device__ __align__(256) __nv_bfloat16 g_Ah[2][BATCH * UNITS];   // h split-high, per parity
__device__ __align__(256) __nv_bfloat16 g_Al[2][BATCH * UNITS];   // h split-low
__device__ __align__(256) __nv_bfloat16 g_Bh[WCOLS * KPAD];       // weights hi, rows n=4u+g, K-contig
__device__ __align__(256) __nv_bfloat16 g_Bl[WCOLS * KPAD];       // weights lo
__device__ __align__(256) __nv_bfloat16 g_xh[TSTEPS * BATCH * 64];// x hi, padded to 64 cols
__device__ __align__(256) __nv_bfloat16 g_xl[TSTEPS * BATCH * 64];
__device__ unsigned char g_mask[TSTEPS * BATCH];
__device__ __align__(256) float g_br[WCOLS];                      // gate-interleaved bias
__device__ __align__(256) float g_p[BATCH * FEATS];
__device__ __align__(256) __nv_bfloat16 g_ph[BATCH * 64];         // AR prediction hi (padded)
__device__ __align__(256) __nv_bfloat16 g_pl[BATCH * 64];
__device__ __align__(256) float g_d1[BATCH * 256];
__device__ __align__(256) float g_d2[BATCH * 128];
__device__ __align__(256) float g_d3[BATCH * 64];

// ---------------- PTX helpers (sm_80+ features only) ----------------
__device__ __forceinline__ u32 su32(const void* p) {
    return (u32)__cvta_generic_to_shared(p);
}
__device__ __forceinline__ void cpasync16(u32 dst, const void* src) {
    asm volatile("cp.async.cg.shared.global [%0], [%1], 16;" :: "r"(dst), "l"(src) : "memory");
}
#define CP_COMMIT() asm volatile("cp.async.commit_group;" ::: "memory")
#define CP_WAIT_1() asm volatile("cp.async.wait_group 1;" ::: "memory")
#define CP_WAIT_0() asm volatile("cp.async.wait_group 0;" ::: "memory")

__device__ __forceinline__ void ldsm4(u32& r0, u32& r1, u32& r2, u32& r3, u32 addr) {
    asm volatile("ldmatrix.sync.aligned.m8n8.x4.shared.b16 {%0,%1,%2,%3}, [%4];"
                 : "=r"(r0), "=r"(r1), "=r"(r2), "=r"(r3) : "r"(addr));
}
__device__ __forceinline__ void hmma(float* d, const u32* a, const u32* b) {
    asm("mma.sync.aligned.m16n8k16.row.col.f32.bf16.bf16.f32 "
        "{%0,%1,%2,%3}, {%4,%5,%6,%7}, {%8,%9}, {%0,%1,%2,%3};"
        : "+f"(d[0]), "+f"(d[1]), "+f"(d[2]), "+f"(d[3])
        : "r"(a[0]), "r"(a[1]), "r"(a[2]), "r"(a[3]), "r"(b[0]), "r"(b[1]));
}

// ---------------- prep kernels ----------------
__global__ void init_zero() {
    for (int i = blockIdx.x * blockDim.x + threadIdx.x;
         i < BATCH * UNITS; i += gridDim.x * blockDim.x) {
        g_h[0][i] = 0.f; g_h[1][i] = 0.f;
        g_c[0][i] = 0.f; g_c[1][i] = 0.f;
        g_Ah[0][i] = __float2bfloat16(0.f); g_Ah[1][i] = __float2bfloat16(0.f);
        g_Al[0][i] = __float2bfloat16(0.f); g_Al[1][i] = __float2bfloat16(0.f);
        if (i < BATCH * 64) { g_ph[i] = __float2bfloat16(0.f); g_pl[i] = __float2bfloat16(0.f); }
    }
}

// B[n][k], n = 4u+g (gate-interleaved), k<1024: rec; 1024<=k<1040: input kernel; else 0
__global__ void prep_B(const float* __restrict__ rec, const float* __restrict__ ker,
                       const float* __restrict__ bias) {
    for (int i = blockIdx.x * blockDim.x + threadIdx.x;
         i < WCOLS * KPAD; i += gridDim.x * blockDim.x) {
        int n = i / KPAD, k = i - n * KPAD;
        int u = n >> 2, g = n & 3;
        float w = 0.f;
        if (k < UNITS) w = rec[k * WCOLS + g * UNITS + u];
        else if (k < UNITS + FEATS) w = ker[(k - UNITS) * WCOLS + g * UNITS + u];
        __nv_bfloat16 hi = __float2bfloat16(w);
        g_Bh[i] = hi;
        g_Bl[i] = __float2bfloat16(w - __bfloat162float(hi));
        if (k == 0) g_br[n] = bias[g * UNITS + u];
    }
}

// x hi/lo, padded to 64 cols: g_xh[t][row][c]
__global__ void prep_X(const float* __restrict__ x, int T) {
    for (int i = blockIdx.x * blockDim.x + threadIdx.x;
         i < T * BATCH * 64; i += gridDim.x * blockDim.x) {
        int t = i / (BATCH * 64);
        int r = (i / 64) % BATCH;
        int c = i % 64;
        float v = (c < FEATS) ? x[(r * T + t) * FEATS + c] : 0.f;
        __nv_bfloat16 hi = __float2bfloat16(v);
        g_xh[i] = hi;
        g_xl[i] = __float2bfloat16(v - __bfloat162float(hi));
    }
}

__global__ void prep_mask(const float* __restrict__ x, int T) {
    for (int i = blockIdx.x * blockDim.x + threadIdx.x;
         i < T * BATCH; i += gridDim.x * blockDim.x) {
        int t = i / BATCH, r = i % BATCH;
        int m = 0;
        for (int f = 0; f < FEATS; f++)
            if (x[(r * T + t) * FEATS + f] != MASKV) m = 1;
        g_mask[i] = (unsigned char)m;
    }
}

// ---------------- mma.sync PLSTM step ----------------
// grid (4, 32): CTA = 64 batch rows x 128 gate-cols, 4 warps of 32x64.
// K = 17 chunks of 64 (16 recurrent + 1 x-features). 3 hi/lo passes fused into
// the same register accumulators (Ah*Bh + Ah*Bl + Al*Bh) — each operand loaded once.
// cp.async double-buffered smem, XOR-swizzled for conflict-free ldmatrix.
#define SMEM_DYN (2 * BUFBYTES + 1024)
__global__ void __launch_bounds__(128)
step_mma(const __nv_bfloat16* __restrict__ Ah, const __nv_bfloat16* __restrict__ Al,
         const __nv_bfloat16* __restrict__ Xh, const __nv_bfloat16* __restrict__ Xl,
         const float* __restrict__ tsrc, int tstride, const unsigned char* __restrict__ msk,
         const float* __restrict__ hin, const float* __restrict__ cin,
         float* __restrict__ hout, float* __restrict__ cout,
         __nv_bfloat16* __restrict__ AhO, __nv_bfloat16* __restrict__ AlO,
         const float* __restrict__ period, const float* __restrict__ phase,
         const float* __restrict__ ratio)
{
    extern __shared__ char dsm_raw[];
    char* dsm = (char*)((((uintptr_t)dsm_raw) + 1023) & ~(uintptr_t)1023);
    const u32 dynb = su32(dsm);

    const int tid  = threadIdx.x;
    const int lane = tid & 31, wid = tid >> 5;
    const int warpM = wid & 1, warpN = wid >> 1;
    const int m0 = blockIdx.x * 64;
    const int n0 = blockIdx.y * 128;

    float acc[2][8][4];
    #pragma unroll
    for (int a = 0; a < 2; a++)
        #pragma unroll
        for (int b = 0; b < 8; b++)
            #pragma unroll
            for (int d = 0; d < 4; d++) acc[a][b][d] = 0.f;

    // ldmatrix per-lane geometry
    const int aRowB = warpM * 32 + (lane & 7) + (((lane >> 3) & 1) << 3); // + mt*16
    const int acol  = lane >> 4;                                          // k8 half
    const int bRowB = warpN * 64 + (lane & 7) + ((lane >> 4) << 3);       // + p*16
    const int bcol  = (lane >> 3) & 1;                                    // k8 half

    // fill chunk c into smem buffer (c&1) via cp.async (no reg staging)
    auto fill = [&](int c) {
        const u32 sb = dynb + (c & 1) * BUFBYTES;
        const int kb = c * 64;
        const __nv_bfloat16 *ash, *asl;
        int astride;
        if (c < 16) { ash = Ah + m0 * UNITS + kb; asl = Al + m0 * UNITS + kb; astride = UNITS; }
        else        { ash = Xh + m0 * 64;         asl = Xl + m0 * 64;         astride = 64; }
        #pragma unroll
        for (int q = 0; q < 4; q++) {               // A: 64 rows x 8 chunks, 2 matrices
            int ci = tid + q * 128;
            int row = ci >> 3, cc = ci & 7;
            u32 d = (u32)row * 128 + (u32)((cc ^ (row & 7)) << 4);
            cpasync16(sb + d,        ash + row * astride + cc * 8);
            cpasync16(sb + 8192 + d, asl + row * astride + cc * 8);
        }
        #pragma unroll
        for (int q = 0; q < 8; q++) {               // B: 128 rows x 8 chunks, 2 matrices
            int ci = tid + q * 128;
            int row = ci >> 3, cc = ci & 7;
            u32 d = (u32)row * 128 + (u32)((cc ^ (row & 7)) << 4);
            cpasync16(sb + 16384 + d, g_Bh + (n0 + row) * KPAD + kb + cc * 8);
            cpasync16(sb + 32768 + d, g_Bl + (n0 + row) * KPAD + kb + cc * 8);
        }
    };

    auto compute = [&](int c) {
        const u32 sb = dynb + (c & 1) * BUFBYTES;
        #pragma unroll
        for (int ks = 0; ks < 4; ks++) {
            u32 ahf[2][4], alf[2][4], bhf[8][2], blf[8][2];
            #pragma unroll
            for (int mt = 0; mt < 2; mt++) {
                int r = aRowB + mt * 16;
                int ch = ks * 2 + acol;
                u32 ad = sb + (u32)r * 128 + (u32)((ch ^ (r & 7)) << 4);
                ldsm4(ahf[mt][0], ahf[mt][1], ahf[mt][2], ahf[mt][3], ad);
                ldsm4(alf[mt][0], alf[mt][1], alf[mt][2], alf[mt][3], ad + 8192);
            }
            #pragma unroll
            for (int p = 0; p < 4; p++) {
                int r = bRowB + p * 16;
                int ch = ks * 2 + bcol;
                u32 bd = sb + 16384 + (u32)r * 128 + (u32)((ch ^ (r & 7)) << 4);
                u32 r0, r1, r2, r3;
                ldsm4(r0, r1, r2, r3, bd);
                bhf[2 * p][0] = r0; bhf[2 * p][1] = r1;
                bhf[2 * p + 1][0] = r2; bhf[2 * p + 1][1] = r3;
                ldsm4(r0, r1, r2, r3, bd + 16384);
                blf[2 * p][0] = r0; blf[2 * p][1] = r1;
                blf[2 * p + 1][0] = r2; blf[2 * p + 1][1] = r3;
            }
            #pragma unroll
            for (int mt = 0; mt < 2; mt++)
                #pragma unroll
                for (int nt = 0; nt < 8; nt++) {
                    hmma(acc[mt][nt], ahf[mt], bhf[nt]);   // hi*hi
                    hmma(acc[mt][nt], ahf[mt], blf[nt]);   // hi*lo
                    hmma(acc[mt][nt], alf[mt], bhf[nt]);   // lo*hi
                }
        }
    };

    fill(0);
    CP_COMMIT();
    #pragma unroll 1
    for (int c = 0; c < CHUNKS; c++) {
        if (c + 1 < CHUNKS) { fill(c + 1); CP_COMMIT(); CP_WAIT_1(); }
        else                { CP_WAIT_0(); }
        __syncthreads();
        compute(c);
        __syncthreads();
    }

    // ---- epilogue: shuffle gate pairs together, gates + phased time-gate ----
    #pragma unroll
    for (int mt = 0; mt < 2; mt++) {
        #pragma unroll
        for (int nt = 0; nt < 8; nt++) {
            float d0 = acc[mt][nt][0], d1 = acc[mt][nt][1];
            float d2 = acc[mt][nt][2], d3 = acc[mt][nt][3];
            float v0 = __shfl_xor_sync(0xFFFFFFFFu, d0, 1);
            float v1 = __shfl_xor_sync(0xFFFFFFFFu, d1, 1);
            float v2 = __shfl_xor_sync(0xFFFFFFFFu, d2, 1);
            float v3 = __shfl_xor_sync(0xFFFFFFFFu, d3, 1);
            int odd = lane & 1;
            float zi = odd ? v2 : d0;
            float zf = odd ? v3 : d1;
            float zg = odd ? d2 : v0;
            float zo = odd ? d3 : v1;
            int row = m0 + warpM * 32 + mt * 16 + (lane >> 2) + (odd ? 8 : 0);
            int col = n0 + warpN * 64 + nt * 8 + ((lane & 2) ? 4 : 0);
            int u = col >> 2;
            float4 bb = *(const float4*)(g_br + col);
            zi += bb.x; zf += bb.y; zg += bb.z; zo += bb.w;

            float ig = 1.f / (1.f + expf(-zi));
            float fg = 1.f / (1.f + expf(-zf));
            float gg = tanhf(zg);
            float og = 1.f / (1.f + expf(-zo));
            int idx = row * UNITS + u;
            float ho = hin[idx], co = cin[idx];
            float nc = fg * co + ig * gg;
            float nh = og * tanhf(nc);
            float tval = tsrc[row * tstride];
            float per = period[u], pha = phase[u], ro = ratio[u];
            float cr = fmodf(tval - pha, per);
            if (cr < 0.f) cr += per;
            cr /= per;
            float kg;
            if (cr < 0.5f * ro)      kg = 2.f * cr / ro;
            else if (cr < ro)        kg = 2.f - 2.f * cr / ro;
            else                     kg = LEAKF * cr;
            float h2 = kg * nh + (1.f - kg) * ho;
            float c2 = kg * nc + (1.f - kg) * co;
            if (msk && !msk[row]) { h2 = ho; c2 = co; }
            hout[idx] = h2;
            cout[idx] = c2;
            __nv_bfloat16 hi = __float2bfloat16(h2);
            AhO[idx] = hi;
            AlO[idx] = __float2bfloat16(h2 - __bfloat162float(hi));
        }
    }
}

// -------- generic small dense layer: out = act(A[256,K] @ W[K,N] + b) --------
__global__ void __launch_bounds__(256)
dense_kernel(const float* __restrict__ A, int K,
             const float* __restrict__ W, int N,
             const float* __restrict__ bias,
             float* __restrict__ out, int act,
             float* __restrict__ out2, int out2_stride,
             __nv_bfloat16* __restrict__ ph, __nv_bfloat16* __restrict__ pl)
{
    __shared__ float As[16][16];
    __shared__ float Ws[16][16];
    int tx = threadIdx.x, ty = threadIdx.y;
    int m0 = blockIdx.x * 16, n0 = blockIdx.y * 16;
    float acc = 0.f;
    for (int k0 = 0; k0 < K; k0 += 16) {
        As[ty][tx] = A[(m0 + ty) * K + k0 + tx];
        Ws[ty][tx] = W[(k0 + ty) * N + n0 + tx];
        __syncthreads();
        #pragma unroll
        for (int kk = 0; kk < 16; kk++)
            acc += As[ty][kk] * Ws[kk][tx];
        __syncthreads();
    }
    int n = n0 + tx, mrow = m0 + ty;
    acc += bias[n];
    if (act) acc = tanhf(acc);
    out[mrow * N + n] = acc;
    if (out2) out2[mrow * out2_stride + n] = acc;
    if (ph) {   // AR prediction split for next step's GEMM (only for N=16 final layer)
        __nv_bfloat16 hi = __float2bfloat16(acc);
        ph[mrow * 64 + n] = hi;
        pl[mrow * 64 + n] = __float2bfloat16(acc - __bfloat162float(hi));
    }
}

extern "C" void kernel_launch(void* const* d_in, const int* in_sizes, int n_in,
                              void* d_out, int out_size) {
    const float* x      = (const float*)d_in[0];
    const float* kernel = (const float*)d_in[1];
    const float* rec    = (const float*)d_in[2];
    const float* bias   = (const float*)d_in[3];
    const float* period = (const float*)d_in[4];
    const float* phase  = (const float*)d_in[5];
    const float* ratio  = (const float*)d_in[6];
    const float* w1 = (const float*)d_in[7];  const float* b1 = (const float*)d_in[8];
    const float* w2 = (const float*)d_in[9];  const float* b2 = (const float*)d_in[10];
    const float* w3 = (const float*)d_in[11]; const float* b3 = (const float*)d_in[12];
    const float* wo = (const float*)d_in[13]; const float* bo = (const float*)d_in[14];
    float* out = (float*)d_out;

    const int T = in_sizes[0] / (BATCH * FEATS);   // 512

    float *hb, *cb, *pb, *d1, *d2, *d3;
    __nv_bfloat16 *ahb, *alb, *xhb, *xlb, *phb, *plb;
    unsigned char *mkb;
    cudaGetSymbolAddress((void**)&hb,  g_h);
    cudaGetSymbolAddress((void**)&cb,  g_c);
    cudaGetSymbolAddress((void**)&pb,  g_p);
    cudaGetSymbolAddress((void**)&d1,  g_d1);
    cudaGetSymbolAddress((void**)&d2,  g_d2);
    cudaGetSymbolAddress((void**)&d3,  g_d3);
    cudaGetSymbolAddress((void**)&ahb, g_Ah);
    cudaGetSymbolAddress((void**)&alb, g_Al);
    cudaGetSymbolAddress((void**)&xhb, g_xh);
    cudaGetSymbolAddress((void**)&xlb, g_xl);
    cudaGetSymbolAddress((void**)&phb, g_ph);
    cudaGetSymbolAddress((void**)&plb, g_pl);
    cudaGetSymbolAddress((void**)&mkb, g_mask);

    cudaFuncSetAttribute(step_mma, cudaFuncAttributeMaxDynamicSharedMemorySize, SMEM_DYN);

    init_zero<<<512, 256>>>();
    prep_B<<<4096, 256>>>(rec, kernel, bias);
    prep_X<<<4096, 256>>>(x, T);
    prep_mask<<<512, 256>>>(x, T);

    const dim3 sgrid(BATCH / 64, WCOLS / 128);   // (4, 32)
    const int SU = BATCH * UNITS;
    int par = 0;

    // warm phase: T masked steps
    for (int t = 0; t < T; t++) {
        step_mma<<<sgrid, 128, SMEM_DYN>>>(
            ahb + par * SU, alb + par * SU,
            xhb + t * BATCH * 64, xlb + t * BATCH * 64,
            x + t * FEATS, T * FEATS, mkb + t * BATCH,
            hb + par * SU, cb + par * SU,
            hb + (par ^ 1) * SU, cb + (par ^ 1) * SU,
            ahb + (par ^ 1) * SU, alb + (par ^ 1) * SU,
            period, phase, ratio);
        par ^= 1;
    }

    // dense stack: h -> d1 -> d2 -> d3 -> (p, out[:,s,:], p hi/lo)
    auto dense_stack = [&](int s) {
        const float* h = hb + par * SU;
        dense_kernel<<<dim3(16,16), dim3(16,16)>>>(h,  UNITS, w1, 256, b1, d1, 1, nullptr, 0, nullptr, nullptr);
        dense_kernel<<<dim3(16, 8), dim3(16,16)>>>(d1, 256,   w2, 128, b2, d2, 1, nullptr, 0, nullptr, nullptr);
        dense_kernel<<<dim3(16, 4), dim3(16,16)>>>(d2, 128,   w3, 64,  b3, d3, 1, nullptr, 0, nullptr, nullptr);
        dense_kernel<<<dim3(16, 1), dim3(16,16)>>>(d3, 64,    wo, FEATS, bo, pb, 0,
                                                   out + s * FEATS, OUTSTEPS * FEATS, phb, plb);
    };

    dense_stack(0);   // pred0

    // autoregressive phase: 23 unmasked steps fed by p
    for (int s = 1; s < OUTSTEPS; s++) {
        step_mma<<<sgrid, 128, SMEM_DYN>>>(
            ahb + par * SU, alb + par * SU,
            phb, plb,
            pb, FEATS, nullptr,
            hb + par * SU, cb + par * SU,
            hb + (par ^ 1) * SU, cb + (par ^ 1) * SU,
            ahb + (par ^ 1) * SU, alb + (par ^ 1) * SU,
            period, phase, ratio);
        par ^= 1;
        dense_stack(s);
    }
}

// round 11
// speedup vs baseline: 3.9146x; 1.1987x over previous
#include <cuda_runtime.h>
#include <cuda_bf16.h>
#include <cstdint>

// Problem constants (shapes fixed by setup_inputs)
#define BATCH 256
#define UNITS 1024
#define FEATS 16
#define WCOLS 4096          // 4*UNITS
#define OUTSTEPS 24
#define LEAKF 0.001f
#define MASKV (-1.0f)
#define TSTEPS 512
#define KPAD 1088           // 1024 (h) + 64 (x chunk, zero-padded past 16)
#define CHUNKS 17           // K-chunks of 64 (last one: only 16 real cols)
#define BUFBYTES 49152      // Ah 8K + Al 8K + Bh 16K + Bl 16K per stage

#define SMEM_DBUF (2 * BUFBYTES)                 // 98304
#define SMEM_HSTAGE SMEM_DBUF                    // hin stage: 64 rows * 36 floats
#define SMEM_CSTAGE (SMEM_DBUF + 9216)           // cin stage
#define SMEM_DYN (SMEM_DBUF + 2 * 9216 + 1024)   // + align pad

typedef unsigned int u32;
typedef unsigned long long u64;

// -------- device scratch (no allocation allowed) --------
__device__ __align__(256) float g_h[2][BATCH * UNITS];
__device__ __align__(256) float g_c[2][BATCH * UNITS];
__device__ __align__(256) __nv_bfloat16 g_Ah[2][BATCH * UNITS];   // h split-high, per parity
__device__ __align__(256) __nv_bfloat16 g_Al[2][BATCH * UNITS];   // h split-low
__device__ __align__(256) __nv_bfloat16 g_Bh[WCOLS * KPAD];       // weights hi, rows n=4u+g, K-contig
__device__ __align__(256) __nv_bfloat16 g_Bl[WCOLS * KPAD];       // weights lo
__device__ __align__(256) __nv_bfloat16 g_xh[TSTEPS * BATCH * 64];// x hi, padded to 64 cols
__device__ __align__(256) __nv_bfloat16 g_xl[TSTEPS * BATCH * 64];
__device__ unsigned char g_mask[TSTEPS * BATCH];
__device__ __align__(256) float g_br[WCOLS];                      // gate-interleaved bias
__device__ __align__(256) float g_p[BATCH * FEATS];
__device__ __align__(256) __nv_bfloat16 g_ph[BATCH * 64];         // AR prediction hi (padded)
__device__ __align__(256) __nv_bfloat16 g_pl[BATCH * 64];
__device__ __align__(256) float g_d1[BATCH * 256];
__device__ __align__(256) float g_d2[BATCH * 128];
__device__ __align__(256) float g_d3[BATCH * 64];

// ---------------- PTX helpers (sm_80+ features only) ----------------
__device__ __forceinline__ u32 su32(const void* p) {
    return (u32)__cvta_generic_to_shared(p);
}
__device__ __forceinline__ void cpasync16(u32 dst, const void* src) {
    asm volatile("cp.async.cg.shared.global [%0], [%1], 16;" :: "r"(dst), "l"(src) : "memory");
}
#define CP_COMMIT() asm volatile("cp.async.commit_group;" ::: "memory")
#define CP_WAIT_1() asm volatile("cp.async.wait_group 1;" ::: "memory")
#define CP_WAIT_0() asm volatile("cp.async.wait_group 0;" ::: "memory")

__device__ __forceinline__ void ldsm4(u32& r0, u32& r1, u32& r2, u32& r3, u32 addr) {
    asm volatile("ldmatrix.sync.aligned.m8n8.x4.shared.b16 {%0,%1,%2,%3}, [%4];"
                 : "=r"(r0), "=r"(r1), "=r"(r2), "=r"(r3) : "r"(addr));
}
__device__ __forceinline__ void hmma(float* d, const u32* a, const u32* b) {
    asm("mma.sync.aligned.m16n8k16.row.col.f32.bf16.bf16.f32 "
        "{%0,%1,%2,%3}, {%4,%5,%6,%7}, {%8,%9}, {%0,%1,%2,%3};"
        : "+f"(d[0]), "+f"(d[1]), "+f"(d[2]), "+f"(d[3])
        : "r"(a[0]), "r"(a[1]), "r"(a[2]), "r"(a[3]), "r"(b[0]), "r"(b[1]));
}

// ---------------- prep kernels ----------------
__global__ void init_zero() {
    for (int i = blockIdx.x * blockDim.x + threadIdx.x;
         i < BATCH * UNITS; i += gridDim.x * blockDim.x) {
        g_h[0][i] = 0.f; g_h[1][i] = 0.f;
        g_c[0][i] = 0.f; g_c[1][i] = 0.f;
        g_Ah[0][i] = __float2bfloat16(0.f); g_Ah[1][i] = __float2bfloat16(0.f);
        g_Al[0][i] = __float2bfloat16(0.f); g_Al[1][i] = __float2bfloat16(0.f);
        if (i < BATCH * 64) { g_ph[i] = __float2bfloat16(0.f); g_pl[i] = __float2bfloat16(0.f); }
    }
}

// B[n][k], n = 4u+g (gate-interleaved), k<1024: rec; 1024<=k<1040: input kernel; else 0
__global__ void prep_B(const float* __restrict__ rec, const float* __restrict__ ker,
                       const float* __restrict__ bias) {
    for (int i = blockIdx.x * blockDim.x + threadIdx.x;
         i < WCOLS * KPAD; i += gridDim.x * blockDim.x) {
        int n = i / KPAD, k = i - n * KPAD;
        int u = n >> 2, g = n & 3;
        float w = 0.f;
        if (k < UNITS) w = rec[k * WCOLS + g * UNITS + u];
        else if (k < UNITS + FEATS) w = ker[(k - UNITS) * WCOLS + g * UNITS + u];
        __nv_bfloat16 hi = __float2bfloat16(w);
        g_Bh[i] = hi;
        g_Bl[i] = __float2bfloat16(w - __bfloat162float(hi));
        if (k == 0) g_br[n] = bias[g * UNITS + u];
    }
}

// x hi/lo, padded to 64 cols: g_xh[t][row][c]
__global__ void prep_X(const float* __restrict__ x, int T) {
    for (int i = blockIdx.x * blockDim.x + threadIdx.x;
         i < T * BATCH * 64; i += gridDim.x * blockDim.x) {
        int t = i / (BATCH * 64);
        int r = (i / 64) % BATCH;
        int c = i % 64;
        float v = (c < FEATS) ? x[(r * T + t) * FEATS + c] : 0.f;
        __nv_bfloat16 hi = __float2bfloat16(v);
        g_xh[i] = hi;
        g_xl[i] = __float2bfloat16(v - __bfloat162float(hi));
    }
}

__global__ void prep_mask(const float* __restrict__ x, int T) {
    for (int i = blockIdx.x * blockDim.x + threadIdx.x;
         i < T * BATCH; i += gridDim.x * blockDim.x) {
        int t = i / BATCH, r = i % BATCH;
        int m = 0;
        for (int f = 0; f < FEATS; f++)
            if (x[(r * T + t) * FEATS + f] != MASKV) m = 1;
        g_mask[i] = (unsigned char)m;
    }
}

// ---------------- mma.sync PLSTM step ----------------
// grid (4, 32): CTA = 64 batch rows x 128 gate-cols, 8 warps of 32x32 (2M x 4N).
// K = 16 chunks of 64 (recurrent) + 1 chunk of 16 (x features). 3 hi/lo passes
// fused into the same register accumulators (Ah*Bh + Ah*Bl + Al*Bh).
// cp.async double-buffered smem, XOR-swizzled for conflict-free ldmatrix.
// h/c state prefetched to smem at start; epilogue staged via smem, coalesced I/O.
__global__ void __launch_bounds__(256)
step_mma(const __nv_bfloat16* __restrict__ Ah, const __nv_bfloat16* __restrict__ Al,
         const __nv_bfloat16* __restrict__ Xh, const __nv_bfloat16* __restrict__ Xl,
         const float* __restrict__ tsrc, int tstride, const unsigned char* __restrict__ msk,
         const float* __restrict__ hin, const float* __restrict__ cin,
         float* __restrict__ hout, float* __restrict__ cout,
         __nv_bfloat16* __restrict__ AhO, __nv_bfloat16* __restrict__ AlO,
         const float* __restrict__ period, const float* __restrict__ phase,
         const float* __restrict__ ratio)
{
    extern __shared__ char dsm_raw[];
    char* dsm = (char*)((((uintptr_t)dsm_raw) + 1023) & ~(uintptr_t)1023);
    const u32 dynb = su32(dsm);

    const int tid  = threadIdx.x;
    const int lane = tid & 31, wid = tid >> 5;
    const int warpM = wid & 1, warpN = wid >> 1;     // 2 M-warps x 4 N-warps
    const int m0 = blockIdx.x * 64;
    const int n0 = blockIdx.y * 128;
    const int u0 = n0 >> 2;

    float* s_hin = (float*)(dsm + SMEM_HSTAGE);      // [64][36] padded
    float* s_cin = (float*)(dsm + SMEM_CSTAGE);

    // ---- prefetch h/c state (coalesced; overlaps the whole MMA loop) ----
    #pragma unroll
    for (int q = 0; q < 2; q++) {
        int ci = tid + q * 256;            // 0..511 : 64 rows x 8 chunks of 4 floats
        int row = ci >> 3, c4 = ci & 7;
        cpasync16(dynb + SMEM_HSTAGE + (u32)(row * 36 + c4 * 4) * 4,
                  hin + (m0 + row) * UNITS + u0 + c4 * 4);
        cpasync16(dynb + SMEM_CSTAGE + (u32)(row * 36 + c4 * 4) * 4,
                  cin + (m0 + row) * UNITS + u0 + c4 * 4);
    }

    float acc[2][4][4];
    #pragma unroll
    for (int a = 0; a < 2; a++)
        #pragma unroll
        for (int b = 0; b < 4; b++)
            #pragma unroll
            for (int d = 0; d < 4; d++) acc[a][b][d] = 0.f;

    // ldmatrix per-lane geometry
    const int aRowB = warpM * 32 + (lane & 7) + (((lane >> 3) & 1) << 3); // + mt*16
    const int acol  = lane >> 4;                                          // k8 half
    const int bRowB = warpN * 32 + (lane & 7) + ((lane >> 4) << 3);       // + p*16
    const int bcol  = (lane >> 3) & 1;                                    // k8 half

    // fill chunk c into smem buffer (c&1) via cp.async
    auto fill = [&](int c) {
        const u32 sb = dynb + (c & 1) * BUFBYTES;
        if (c < 16) {
            const int kb = c * 64;
            #pragma unroll
            for (int q = 0; q < 2; q++) {           // A: 64 rows x 8 chunks, hi+lo
                int ci = tid + q * 256;
                int row = ci >> 3, cc = ci & 7;
                u32 d = (u32)row * 128 + (u32)((cc ^ (row & 7)) << 4);
                cpasync16(sb + d,        Ah + (m0 + row) * UNITS + kb + cc * 8);
                cpasync16(sb + 8192 + d, Al + (m0 + row) * UNITS + kb + cc * 8);
            }
            #pragma unroll
            for (int q = 0; q < 4; q++) {           // B: 128 rows x 8 chunks, hi+lo
                int ci = tid + q * 256;
                int row = ci >> 3, cc = ci & 7;
                u32 d = (u32)row * 128 + (u32)((cc ^ (row & 7)) << 4);
                cpasync16(sb + 16384 + d, g_Bh + (n0 + row) * KPAD + kb + cc * 8);
                cpasync16(sb + 32768 + d, g_Bl + (n0 + row) * KPAD + kb + cc * 8);
            }
        } else {
            // x chunk: only first 16 K-cols are real (2 chunks of 8 bf16)
            if (tid < 128) {                        // A: 64 rows x 2 chunks
                int row = tid >> 1, cc = tid & 1;
                u32 d = (u32)row * 128 + (u32)((cc ^ (row & 7)) << 4);
                cpasync16(sb + d,        Xh + (m0 + row) * 64 + cc * 8);
                cpasync16(sb + 8192 + d, Xl + (m0 + row) * 64 + cc * 8);
            }
            {                                        // B: 128 rows x 2 chunks
                int row = tid >> 1, cc = tid & 1;
                u32 d = (u32)row * 128 + (u32)((cc ^ (row & 7)) << 4);
                cpasync16(sb + 16384 + d, g_Bh + (n0 + row) * KPAD + 1024 + cc * 8);
                cpasync16(sb + 32768 + d, g_Bl + (n0 + row) * KPAD + 1024 + cc * 8);
            }
        }
    };

    auto computeKs = [&](u32 sb, int ks) {
        u32 ahf[2][4], alf[2][4], bhf[4][2], blf[4][2];
        #pragma unroll
        for (int mt = 0; mt < 2; mt++) {
            int r = aRowB + mt * 16;
            int ch = ks * 2 + acol;
            u32 ad = sb + (u32)r * 128 + (u32)((ch ^ (r & 7)) << 4);
            ldsm4(ahf[mt][0], ahf[mt][1], ahf[mt][2], ahf[mt][3], ad);
            ldsm4(alf[mt][0], alf[mt][1], alf[mt][2], alf[mt][3], ad + 8192);
        }
        #pragma unroll
        for (int p = 0; p < 2; p++) {
            int r = bRowB + p * 16;
            int ch = ks * 2 + bcol;
            u32 bd = sb + 16384 + (u32)r * 128 + (u32)((ch ^ (r & 7)) << 4);
            u32 r0, r1, r2, r3;
            ldsm4(r0, r1, r2, r3, bd);
            bhf[2 * p][0] = r0; bhf[2 * p][1] = r1;
            bhf[2 * p + 1][0] = r2; bhf[2 * p + 1][1] = r3;
            ldsm4(r0, r1, r2, r3, bd + 16384);
            blf[2 * p][0] = r0; blf[2 * p][1] = r1;
            blf[2 * p + 1][0] = r2; blf[2 * p + 1][1] = r3;
        }
        #pragma unroll
        for (int mt = 0; mt < 2; mt++)
            #pragma unroll
            for (int nt = 0; nt < 4; nt++) {
                hmma(acc[mt][nt], ahf[mt], bhf[nt]);   // hi*hi
                hmma(acc[mt][nt], ahf[mt], blf[nt]);   // hi*lo
                hmma(acc[mt][nt], alf[mt], bhf[nt]);   // lo*hi
            }
    };

    fill(0);
    CP_COMMIT();
    #pragma unroll 1
    for (int c = 0; c < CHUNKS; c++) {
        if (c + 1 < CHUNKS) { fill(c + 1); CP_COMMIT(); CP_WAIT_1(); }
        else                { CP_WAIT_0(); }
        __syncthreads();
        const u32 sb = dynb + (c & 1) * BUFBYTES;
        if (c < 16) {
            #pragma unroll
            for (int ks = 0; ks < 4; ks++) computeKs(sb, ks);
        } else {
            computeKs(sb, 0);
        }
        __syncthreads();
    }

    // ---- epilogue: gates + phased time-gate, staged via smem ----
    float* s_oh = (float*)(dsm + 0);                 // [64][33]
    float* s_oc = (float*)(dsm + 8448);              // [64][33]
    __nv_bfloat16* s_ah = (__nv_bfloat16*)(dsm + 16896);  // [64][33]
    __nv_bfloat16* s_al = (__nv_bfloat16*)(dsm + 21120);  // [64][33]

    #pragma unroll
    for (int mt = 0; mt < 2; mt++) {
        #pragma unroll
        for (int nt = 0; nt < 4; nt++) {
            float d0 = acc[mt][nt][0], d1 = acc[mt][nt][1];
            float d2 = acc[mt][nt][2], d3 = acc[mt][nt][3];
            float v0 = __shfl_xor_sync(0xFFFFFFFFu, d0, 1);
            float v1 = __shfl_xor_sync(0xFFFFFFFFu, d1, 1);
            float v2 = __shfl_xor_sync(0xFFFFFFFFu, d2, 1);
            float v3 = __shfl_xor_sync(0xFFFFFFFFu, d3, 1);
            int odd = lane & 1;
            float zi = odd ? v2 : d0;
            float zf = odd ? v3 : d1;
            float zg = odd ? d2 : v0;
            float zo = odd ? d3 : v1;
            int rr = warpM * 32 + mt * 16 + (lane >> 2) + (odd ? 8 : 0);
            int colL = warpN * 32 + nt * 8 + ((lane & 2) ? 4 : 0);  // CTA-local gate col
            int cu = colL >> 2;                                      // CTA-local unit
            int u = u0 + cu;                                         // global unit
            float4 bb = *(const float4*)(g_br + n0 + colL);
            zi += bb.x; zf += bb.y; zg += bb.z; zo += bb.w;

            float ig = 1.f / (1.f + expf(-zi));
            float fg = 1.f / (1.f + expf(-zf));
            float gg = tanhf(zg);
            float og = 1.f / (1.f + expf(-zo));
            float ho = s_hin[rr * 36 + cu], co = s_cin[rr * 36 + cu];
            float nc = fg * co + ig * gg;
            float nh = og * tanhf(nc);
            int grow = m0 + rr;
            float tval = tsrc[grow * tstride];
            float per = period[u], pha = phase[u], ro = ratio[u];
            float cr = fmodf(tval - pha, per);
            if (cr < 0.f) cr += per;
            cr /= per;
            float kg;
            if (cr < 0.5f * ro)      kg = 2.f * cr / ro;
            else if (cr < ro)        kg = 2.f - 2.f * cr / ro;
            else                     kg = LEAKF * cr;
            float h2 = kg * nh + (1.f - kg) * ho;
            float c2 = kg * nc + (1.f - kg) * co;
            if (msk && !msk[grow]) { h2 = ho; c2 = co; }
            s_oh[rr * 33 + cu] = h2;
            s_oc[rr * 33 + cu] = c2;
            __nv_bfloat16 hi = __float2bfloat16(h2);
            s_ah[rr * 33 + cu] = hi;
            s_al[rr * 33 + cu] = __float2bfloat16(h2 - __bfloat162float(hi));
        }
    }
    __syncthreads();

    // coalesced writeback: 64 rows x 32 units per CTA
    #pragma unroll
    for (int q = 0; q < 8; q++) {
        int idx = tid + q * 256;             // 0..2047
        int row = idx >> 5, cu = idx & 31;
        int gidx = (m0 + row) * UNITS + u0 + cu;
        hout[gidx] = s_oh[row * 33 + cu];
        cout[gidx] = s_oc[row * 33 + cu];
        AhO[gidx]  = s_ah[row * 33 + cu];
        AlO[gidx]  = s_al[row * 33 + cu];
    }
}

// -------- generic small dense layer: out = act(A[256,K] @ W[K,N] + b) --------
__global__ void __launch_bounds__(256)
dense_kernel(const float* __restrict__ A, int K,
             const float* __restrict__ W, int N,
             const float* __restrict__ bias,
             float* __restrict__ out, int act,
             float* __restrict__ out2, int out2_stride,
             __nv_bfloat16* __restrict__ ph, __nv_bfloat16* __restrict__ pl)
{
    __shared__ float As[16][16];
    __shared__ float Ws[16][16];
    int tx = threadIdx.x, ty = threadIdx.y;
    int m0 = blockIdx.x * 16, n0 = blockIdx.y * 16;
    float acc = 0.f;
    for (int k0 = 0; k0 < K; k0 += 16) {
        As[ty][tx] = A[(m0 + ty) * K + k0 + tx];
        Ws[ty][tx] = W[(k0 + ty) * N + n0 + tx];
        __syncthreads();
        #pragma unroll
        for (int kk = 0; kk < 16; kk++)
            acc += As[ty][kk] * Ws[kk][tx];
        __syncthreads();
    }
    int n = n0 + tx, mrow = m0 + ty;
    acc += bias[n];
    if (act) acc = tanhf(acc);
    out[mrow * N + n] = acc;
    if (out2) out2[mrow * out2_stride + n] = acc;
    if (ph) {   // AR prediction split for next step's GEMM (only for N=16 final layer)
        __nv_bfloat16 hi = __float2bfloat16(acc);
        ph[mrow * 64 + n] = hi;
        pl[mrow * 64 + n] = __float2bfloat16(acc - __bfloat162float(hi));
    }
}

extern "C" void kernel_launch(void* const* d_in, const int* in_sizes, int n_in,
                              void* d_out, int out_size) {
    const float* x      = (const float*)d_in[0];
    const float* kernel = (const float*)d_in[1];
    const float* rec    = (const float*)d_in[2];
    const float* bias   = (const float*)d_in[3];
    const float* period = (const float*)d_in[4];
    const float* phase  = (const float*)d_in[5];
    const float* ratio  = (const float*)d_in[6];
    const float* w1 = (const float*)d_in[7];  const float* b1 = (const float*)d_in[8];
    const float* w2 = (const float*)d_in[9];  const float* b2 = (const float*)d_in[10];
    const float* w3 = (const float*)d_in[11]; const float* b3 = (const float*)d_in[12];
    const float* wo = (const float*)d_in[13]; const float* bo = (const float*)d_in[14];
    float* out = (float*)d_out;

    const int T = in_sizes[0] / (BATCH * FEATS);   // 512

    float *hb, *cb, *pb, *d1, *d2, *d3;
    __nv_bfloat16 *ahb, *alb, *xhb, *xlb, *phb, *plb;
    unsigned char *mkb;
    cudaGetSymbolAddress((void**)&hb,  g_h);
    cudaGetSymbolAddress((void**)&cb,  g_c);
    cudaGetSymbolAddress((void**)&pb,  g_p);
    cudaGetSymbolAddress((void**)&d1,  g_d1);
    cudaGetSymbolAddress((void**)&d2,  g_d2);
    cudaGetSymbolAddress((void**)&d3,  g_d3);
    cudaGetSymbolAddress((void**)&ahb, g_Ah);
    cudaGetSymbolAddress((void**)&alb, g_Al);
    cudaGetSymbolAddress((void**)&xhb, g_xh);
    cudaGetSymbolAddress((void**)&xlb, g_xl);
    cudaGetSymbolAddress((void**)&phb, g_ph);
    cudaGetSymbolAddress((void**)&plb, g_pl);
    cudaGetSymbolAddress((void**)&mkb, g_mask);

    cudaFuncSetAttribute(step_mma, cudaFuncAttributeMaxDynamicSharedMemorySize, SMEM_DYN);

    init_zero<<<512, 256>>>();
    prep_B<<<4096, 256>>>(rec, kernel, bias);
    prep_X<<<4096, 256>>>(x, T);
    prep_mask<<<512, 256>>>(x, T);

    const dim3 sgrid(BATCH / 64, WCOLS / 128);   // (4, 32)
    const int SU = BATCH * UNITS;
    int par = 0;

    // warm phase: T masked steps
    for (int t = 0; t < T; t++) {
        step_mma<<<sgrid, 256, SMEM_DYN>>>(
            ahb + par * SU, alb + par * SU,
            xhb + t * BATCH * 64, xlb + t * BATCH * 64,
            x + t * FEATS, T * FEATS, mkb + t * BATCH,
            hb + par * SU, cb + par * SU,
            hb + (par ^ 1) * SU, cb + (par ^ 1) * SU,
            ahb + (par ^ 1) * SU, alb + (par ^ 1) * SU,
            period, phase, ratio);
        par ^= 1;
    }

    // dense stack: h -> d1 -> d2 -> d3 -> (p, out[:,s,:], p hi/lo)
    auto dense_stack = [&](int s) {
        const float* h = hb + par * SU;
        dense_kernel<<<dim3(16,16), dim3(16,16)>>>(h,  UNITS, w1, 256, b1, d1, 1, nullptr, 0, nullptr, nullptr);
        dense_kernel<<<dim3(16, 8), dim3(16,16)>>>(d1, 256,   w2, 128, b2, d2, 1, nullptr, 0, nullptr, nullptr);
        dense_kernel<<<dim3(16, 4), dim3(16,16)>>>(d2, 128,   w3, 64,  b3, d3, 1, nullptr, 0, nullptr, nullptr);
        dense_kernel<<<dim3(16, 1), dim3(16,16)>>>(d3, 64,    wo, FEATS, bo, pb, 0,
                                                   out + s * FEATS, OUTSTEPS * FEATS, phb, plb);
    };

    dense_stack(0);   // pred0

    // autoregressive phase: 23 unmasked steps fed by p
    for (int s = 1; s < OUTSTEPS; s++) {
        step_mma<<<sgrid, 256, SMEM_DYN>>>(
            ahb + par * SU, alb + par * SU,
            phb, plb,
            pb, FEATS, nullptr,
            hb + par * SU, cb + par * SU,
            hb + (par ^ 1) * SU, cb + (par ^ 1) * SU,
            ahb + (par ^ 1) * SU, alb + (par ^ 1) * SU,
            period, phase, ratio);
        par ^= 1;
        dense_stack(s);
    }
}

// round 14
// speedup vs baseline: 4.0748x; 1.0409x over previous
#include <cuda_runtime.h>
#include <cuda_bf16.h>
#include <cstdint>

// Problem constants (shapes fixed by setup_inputs)
#define BATCH 256
#define UNITS 1024
#define FEATS 16
#define WCOLS 4096          // 4*UNITS
#define OUTSTEPS 24
#define LEAKF 0.001f
#define MASKV (-1.0f)
#define TSTEPS 512
#define KPAD 1088           // 1024 (h) + 64 (x chunk, zero-padded past 16)
#define CHUNKS 17           // K-chunks of 64 (last one: only 16 real cols)
#define BUFBYTES 49152      // Ah 8K + Al 8K + Bh 16K + Bl 16K per stage
#define NSTAGE 4            // cp.async ring depth

#define SMEM_DBUF (NSTAGE * BUFBYTES)            // 196608
#define SMEM_HSTAGE SMEM_DBUF                    // hin stage: 64 rows * 36 floats
#define SMEM_CSTAGE (SMEM_DBUF + 9216)           // cin stage
#define SMEM_DYN (SMEM_DBUF + 2 * 9216 + 1024)   // + align pad = 216064

typedef unsigned int u32;
typedef unsigned long long u64;

// -------- device scratch (no allocation allowed) --------
__device__ __align__(256) float g_h[2][BATCH * UNITS];
__device__ __align__(256) float g_c[2][BATCH * UNITS];
__device__ __align__(256) __nv_bfloat16 g_Ah[2][BATCH * UNITS];   // h split-high, per parity
__device__ __align__(256) __nv_bfloat16 g_Al[2][BATCH * UNITS];   // h split-low
__device__ __align__(256) __nv_bfloat16 g_Bh[WCOLS * KPAD];       // weights hi, rows n=4u+g, K-contig
__device__ __align__(256) __nv_bfloat16 g_Bl[WCOLS * KPAD];       // weights lo
__device__ __align__(256) __nv_bfloat16 g_xh[TSTEPS * BATCH * 64];// x hi, padded to 64 cols
__device__ __align__(256) __nv_bfloat16 g_xl[TSTEPS * BATCH * 64];
__device__ unsigned char g_mask[TSTEPS * BATCH];
__device__ __align__(256) float g_br[WCOLS];                      // gate-interleaved bias
__device__ __align__(256) float g_p[BATCH * FEATS];
__device__ __align__(256) __nv_bfloat16 g_ph[BATCH * 64];         // AR prediction hi (padded)
__device__ __align__(256) __nv_bfloat16 g_pl[BATCH * 64];
__device__ __align__(256) float g_d1[BATCH * 256];
__device__ __align__(256) float g_d2[BATCH * 128];
__device__ __align__(256) float g_d3[BATCH * 64];

// ---------------- PTX helpers (sm_80+ features only) ----------------
__device__ __forceinline__ u32 su32(const void* p) {
    return (u32)__cvta_generic_to_shared(p);
}
__device__ __forceinline__ void cpasync16(u32 dst, const void* src) {
    asm volatile("cp.async.cg.shared.global [%0], [%1], 16;" :: "r"(dst), "l"(src) : "memory");
}
#define CP_COMMIT() asm volatile("cp.async.commit_group;" ::: "memory")
#define CP_WAIT_2() asm volatile("cp.async.wait_group 2;" ::: "memory")

__device__ __forceinline__ void ldsm4(u32& r0, u32& r1, u32& r2, u32& r3, u32 addr) {
    asm volatile("ldmatrix.sync.aligned.m8n8.x4.shared.b16 {%0,%1,%2,%3}, [%4];"
                 : "=r"(r0), "=r"(r1), "=r"(r2), "=r"(r3) : "r"(addr));
}
__device__ __forceinline__ void hmma(float* d, const u32* a, const u32* b) {
    asm("mma.sync.aligned.m16n8k16.row.col.f32.bf16.bf16.f32 "
        "{%0,%1,%2,%3}, {%4,%5,%6,%7}, {%8,%9}, {%0,%1,%2,%3};"
        : "+f"(d[0]), "+f"(d[1]), "+f"(d[2]), "+f"(d[3])
        : "r"(a[0]), "r"(a[1]), "r"(a[2]), "r"(a[3]), "r"(b[0]), "r"(b[1]));
}

// ---------------- prep kernels ----------------
__global__ void init_zero() {
    for (int i = blockIdx.x * blockDim.x + threadIdx.x;
         i < BATCH * UNITS; i += gridDim.x * blockDim.x) {
        g_h[0][i] = 0.f; g_h[1][i] = 0.f;
        g_c[0][i] = 0.f; g_c[1][i] = 0.f;
        g_Ah[0][i] = __float2bfloat16(0.f); g_Ah[1][i] = __float2bfloat16(0.f);
        g_Al[0][i] = __float2bfloat16(0.f); g_Al[1][i] = __float2bfloat16(0.f);
        if (i < BATCH * 64) { g_ph[i] = __float2bfloat16(0.f); g_pl[i] = __float2bfloat16(0.f); }
    }
}

// B[n][k], n = 4u+g (gate-interleaved), k<1024: rec; 1024<=k<1040: input kernel; else 0
__global__ void prep_B(const float* __restrict__ rec, const float* __restrict__ ker,
                       const float* __restrict__ bias) {
    for (int i = blockIdx.x * blockDim.x + threadIdx.x;
         i < WCOLS * KPAD; i += gridDim.x * blockDim.x) {
        int n = i / KPAD, k = i - n * KPAD;
        int u = n >> 2, g = n & 3;
        float w = 0.f;
        if (k < UNITS) w = rec[k * WCOLS + g * UNITS + u];
        else if (k < UNITS + FEATS) w = ker[(k - UNITS) * WCOLS + g * UNITS + u];
        __nv_bfloat16 hi = __float2bfloat16(w);
        g_Bh[i] = hi;
        g_Bl[i] = __float2bfloat16(w - __bfloat162float(hi));
        if (k == 0) g_br[n] = bias[g * UNITS + u];
    }
}

// x hi/lo, padded to 64 cols: g_xh[t][row][c]
__global__ void prep_X(const float* __restrict__ x, int T) {
    for (int i = blockIdx.x * blockDim.x + threadIdx.x;
         i < T * BATCH * 64; i += gridDim.x * blockDim.x) {
        int t = i / (BATCH * 64);
        int r = (i / 64) % BATCH;
        int c = i % 64;
        float v = (c < FEATS) ? x[(r * T + t) * FEATS + c] : 0.f;
        __nv_bfloat16 hi = __float2bfloat16(v);
        g_xh[i] = hi;
        g_xl[i] = __float2bfloat16(v - __bfloat162float(hi));
    }
}

__global__ void prep_mask(const float* __restrict__ x, int T) {
    for (int i = blockIdx.x * blockDim.x + threadIdx.x;
         i < T * BATCH; i += gridDim.x * blockDim.x) {
        int t = i / BATCH, r = i % BATCH;
        int m = 0;
        for (int f = 0; f < FEATS; f++)
            if (x[(r * T + t) * FEATS + f] != MASKV) m = 1;
        g_mask[i] = (unsigned char)m;
    }
}

// ---------------- mma.sync PLSTM step ----------------
// grid (4, 32): CTA = 64 batch rows x 128 gate-cols, 8 warps of 32x32 (2M x 4N).
// K = 16 chunks of 64 (recurrent) + 1 chunk of 16 (x features). 3 hi/lo passes
// fused into the same register accumulators (Ah*Bh + Ah*Bl + Al*Bh).
// 4-stage cp.async ring, prefetch distance 2, ONE __syncthreads per chunk:
//   fill(c+2) -> commit -> wait_group 2 -> bar -> compute(c)
// Stage reuse: fill writes (c+2)%4; concurrent readers touch (c-1)%4, c%4,
// (c+1)%4 — all distinct mod 4, so the single barrier is sufficient.
__global__ void __launch_bounds__(256)
step_mma(const __nv_bfloat16* __restrict__ Ah, const __nv_bfloat16* __restrict__ Al,
         const __nv_bfloat16* __restrict__ Xh, const __nv_bfloat16* __restrict__ Xl,
         const float* __restrict__ tsrc, int tstride, const unsigned char* __restrict__ msk,
         const float* __restrict__ hin, const float* __restrict__ cin,
         float* __restrict__ hout, float* __restrict__ cout,
         __nv_bfloat16* __restrict__ AhO, __nv_bfloat16* __restrict__ AlO,
         const float* __restrict__ period, const float* __restrict__ phase,
         const float* __restrict__ ratio)
{
    extern __shared__ char dsm_raw[];
    char* dsm = (char*)((((uintptr_t)dsm_raw) + 1023) & ~(uintptr_t)1023);
    const u32 dynb = su32(dsm);

    const int tid  = threadIdx.x;
    const int lane = tid & 31, wid = tid >> 5;
    const int warpM = wid & 1, warpN = wid >> 1;     // 2 M-warps x 4 N-warps
    const int m0 = blockIdx.x * 64;
    const int n0 = blockIdx.y * 128;
    const int u0 = n0 >> 2;

    float* s_hin = (float*)(dsm + SMEM_HSTAGE);      // [64][36] padded
    float* s_cin = (float*)(dsm + SMEM_CSTAGE);

    float acc[2][4][4];
    #pragma unroll
    for (int a = 0; a < 2; a++)
        #pragma unroll
        for (int b = 0; b < 4; b++)
            #pragma unroll
            for (int d = 0; d < 4; d++) acc[a][b][d] = 0.f;

    // ldmatrix per-lane geometry
    const int aRowB = warpM * 32 + (lane & 7) + (((lane >> 3) & 1) << 3); // + mt*16
    const int acol  = lane >> 4;                                          // k8 half
    const int bRowB = warpN * 32 + (lane & 7) + ((lane >> 4) << 3);       // + p*16
    const int bcol  = (lane >> 3) & 1;                                    // k8 half

    // fill chunk c into smem stage (c % NSTAGE) via cp.async
    auto fill = [&](int c) {
        const u32 sb = dynb + (c & (NSTAGE - 1)) * BUFBYTES;
        if (c < 16) {
            const int kb = c * 64;
            #pragma unroll
            for (int q = 0; q < 2; q++) {           // A: 64 rows x 8 chunks, hi+lo
                int ci = tid + q * 256;
                int row = ci >> 3, cc = ci & 7;
                u32 d = (u32)row * 128 + (u32)((cc ^ (row & 7)) << 4);
                cpasync16(sb + d,        Ah + (m0 + row) * UNITS + kb + cc * 8);
                cpasync16(sb + 8192 + d, Al + (m0 + row) * UNITS + kb + cc * 8);
            }
            #pragma unroll
            for (int q = 0; q < 4; q++) {           // B: 128 rows x 8 chunks, hi+lo
                int ci = tid + q * 256;
                int row = ci >> 3, cc = ci & 7;
                u32 d = (u32)row * 128 + (u32)((cc ^ (row & 7)) << 4);
                cpasync16(sb + 16384 + d, g_Bh + (n0 + row) * KPAD + kb + cc * 8);
                cpasync16(sb + 32768 + d, g_Bl + (n0 + row) * KPAD + kb + cc * 8);
            }
        } else {
            // x chunk: only first 16 K-cols are real (2 chunks of 8 bf16)
            if (tid < 128) {                        // A: 64 rows x 2 chunks
                int row = tid >> 1, cc = tid & 1;
                u32 d = (u32)row * 128 + (u32)((cc ^ (row & 7)) << 4);
                cpasync16(sb + d,        Xh + (m0 + row) * 64 + cc * 8);
                cpasync16(sb + 8192 + d, Xl + (m0 + row) * 64 + cc * 8);
            }
            {                                        // B: 128 rows x 2 chunks
                int row = tid >> 1, cc = tid & 1;
                u32 d = (u32)row * 128 + (u32)((cc ^ (row & 7)) << 4);
                cpasync16(sb + 16384 + d, g_Bh + (n0 + row) * KPAD + 1024 + cc * 8);
                cpasync16(sb + 32768 + d, g_Bl + (n0 + row) * KPAD + 1024 + cc * 8);
            }
        }
    };

    auto computeKs = [&](u32 sb, int ks) {
        u32 ahf[2][4], alf[2][4], bhf[4][2], blf[4][2];
        #pragma unroll
        for (int mt = 0; mt < 2; mt++) {
            int r = aRowB + mt * 16;
            int ch = ks * 2 + acol;
            u32 ad = sb + (u32)r * 128 + (u32)((ch ^ (r & 7)) << 4);
            ldsm4(ahf[mt][0], ahf[mt][1], ahf[mt][2], ahf[mt][3], ad);
            ldsm4(alf[mt][0], alf[mt][1], alf[mt][2], alf[mt][3], ad + 8192);
        }
        #pragma unroll
        for (int p = 0; p < 2; p++) {
            int r = bRowB + p * 16;
            int ch = ks * 2 + bcol;
            u32 bd = sb + 16384 + (u32)r * 128 + (u32)((ch ^ (r & 7)) << 4);
            u32 r0, r1, r2, r3;
            ldsm4(r0, r1, r2, r3, bd);
            bhf[2 * p][0] = r0; bhf[2 * p][1] = r1;
            bhf[2 * p + 1][0] = r2; bhf[2 * p + 1][1] = r3;
            ldsm4(r0, r1, r2, r3, bd + 16384);
            blf[2 * p][0] = r0; blf[2 * p][1] = r1;
            blf[2 * p + 1][0] = r2; blf[2 * p + 1][1] = r3;
        }
        #pragma unroll
        for (int mt = 0; mt < 2; mt++)
            #pragma unroll
            for (int nt = 0; nt < 4; nt++) {
                hmma(acc[mt][nt], ahf[mt], bhf[nt]);   // hi*hi
                hmma(acc[mt][nt], ahf[mt], blf[nt]);   // hi*lo
                hmma(acc[mt][nt], alf[mt], bhf[nt]);   // lo*hi
            }
    };

    // ---- prologue: fill(0), fill(1) + h/c state prefetch ----
    fill(0);
    CP_COMMIT();                       // group 0
    fill(1);
    #pragma unroll
    for (int q = 0; q < 2; q++) {      // h/c state (needed only at epilogue)
        int ci = tid + q * 256;        // 64 rows x 8 chunks of 4 floats
        int row = ci >> 3, c4 = ci & 7;
        cpasync16(dynb + SMEM_HSTAGE + (u32)(row * 36 + c4 * 4) * 4,
                  hin + (m0 + row) * UNITS + u0 + c4 * 4);
        cpasync16(dynb + SMEM_CSTAGE + (u32)(row * 36 + c4 * 4) * 4,
                  cin + (m0 + row) * UNITS + u0 + c4 * 4);
    }
    CP_COMMIT();                       // group 1 (fill 1 + state)

    // ---- main loop: one barrier per chunk ----
    #pragma unroll 1
    for (int c = 0; c < CHUNKS; c++) {
        if (c + 2 < CHUNKS) fill(c + 2);
        CP_COMMIT();                   // group c+2 (possibly empty at tail)
        CP_WAIT_2();                   // own groups through c complete
        __syncthreads();               // cross-thread visibility + stage-reuse safety
        const u32 sb = dynb + (c & (NSTAGE - 1)) * BUFBYTES;
        if (c < 16) {
            #pragma unroll
            for (int ks = 0; ks < 4; ks++) computeKs(sb, ks);
        } else {
            computeKs(sb, 0);
        }
    }
    __syncthreads();                   // all computes done before staging epilogue

    // ---- epilogue: gates + phased time-gate, staged via smem ----
    float* s_oh = (float*)(dsm + 0);                 // [64][33]
    float* s_oc = (float*)(dsm + 8448);              // [64][33]
    __nv_bfloat16* s_ah = (__nv_bfloat16*)(dsm + 16896);  // [64][33]
    __nv_bfloat16* s_al = (__nv_bfloat16*)(dsm + 21120);  // [64][33]

    #pragma unroll
    for (int mt = 0; mt < 2; mt++) {
        #pragma unroll
        for (int nt = 0; nt < 4; nt++) {
            float d0 = acc[mt][nt][0], d1 = acc[mt][nt][1];
            float d2 = acc[mt][nt][2], d3 = acc[mt][nt][3];
            float v0 = __shfl_xor_sync(0xFFFFFFFFu, d0, 1);
            float v1 = __shfl_xor_sync(0xFFFFFFFFu, d1, 1);
            float v2 = __shfl_xor_sync(0xFFFFFFFFu, d2, 1);
            float v3 = __shfl_xor_sync(0xFFFFFFFFu, d3, 1);
            int odd = lane & 1;
            float zi = odd ? v2 : d0;
            float zf = odd ? v3 : d1;
            float zg = odd ? d2 : v0;
            float zo = odd ? d3 : v1;
            int rr = warpM * 32 + mt * 16 + (lane >> 2) + (odd ? 8 : 0);
            int colL = warpN * 32 + nt * 8 + ((lane & 2) ? 4 : 0);  // CTA-local gate col
            int cu = colL >> 2;                                      // CTA-local unit
            int u = u0 + cu;                                         // global unit
            float4 bb = *(const float4*)(g_br + n0 + colL);
            zi += bb.x; zf += bb.y; zg += bb.z; zo += bb.w;

            float ig = 1.f / (1.f + expf(-zi));
            float fg = 1.f / (1.f + expf(-zf));
            float gg = tanhf(zg);
            float og = 1.f / (1.f + expf(-zo));
            float ho = s_hin[rr * 36 + cu], co = s_cin[rr * 36 + cu];
            float nc = fg * co + ig * gg;
            float nh = og * tanhf(nc);
            int grow = m0 + rr;
            float tval = tsrc[grow * tstride];
            float per = period[u], pha = phase[u], ro = ratio[u];
            float cr = fmodf(tval - pha, per);
            if (cr < 0.f) cr += per;
            cr /= per;
            float kg;
            if (cr < 0.5f * ro)      kg = 2.f * cr / ro;
            else if (cr < ro)        kg = 2.f - 2.f * cr / ro;
            else                     kg = LEAKF * cr;
            float h2 = kg * nh + (1.f - kg) * ho;
            float c2 = kg * nc + (1.f - kg) * co;
            if (msk && !msk[grow]) { h2 = ho; c2 = co; }
            s_oh[rr * 33 + cu] = h2;
            s_oc[rr * 33 + cu] = c2;
            __nv_bfloat16 hi = __float2bfloat16(h2);
            s_ah[rr * 33 + cu] = hi;
            s_al[rr * 33 + cu] = __float2bfloat16(h2 - __bfloat162float(hi));
        }
    }
    __syncthreads();

    // coalesced writeback: 64 rows x 32 units per CTA
    #pragma unroll
    for (int q = 0; q < 8; q++) {
        int idx = tid + q * 256;             // 0..2047
        int row = idx >> 5, cu = idx & 31;
        int gidx = (m0 + row) * UNITS + u0 + cu;
        hout[gidx] = s_oh[row * 33 + cu];
        cout[gidx] = s_oc[row * 33 + cu];
        AhO[gidx]  = s_ah[row * 33 + cu];
        AlO[gidx]  = s_al[row * 33 + cu];
    }
}

// -------- generic small dense layer: out = act(A[256,K] @ W[K,N] + b) --------
__global__ void __launch_bounds__(256)
dense_kernel(const float* __restrict__ A, int K,
             const float* __restrict__ W, int N,
             const float* __restrict__ bias,
             float* __restrict__ out, int act,
             float* __restrict__ out2, int out2_stride,
             __nv_bfloat16* __restrict__ ph, __nv_bfloat16* __restrict__ pl)
{
    __shared__ float As[16][16];
    __shared__ float Ws[16][16];
    int tx = threadIdx.x, ty = threadIdx.y;
    int m0 = blockIdx.x * 16, n0 = blockIdx.y * 16;
    float acc = 0.f;
    for (int k0 = 0; k0 < K; k0 += 16) {
        As[ty][tx] = A[(m0 + ty) * K + k0 + tx];
        Ws[ty][tx] = W[(k0 + ty) * N + n0 + tx];
        __syncthreads();
        #pragma unroll
        for (int kk = 0; kk < 16; kk++)
            acc += As[ty][kk] * Ws[kk][tx];
        __syncthreads();
    }
    int n = n0 + tx, mrow = m0 + ty;
    acc += bias[n];
    if (act) acc = tanhf(acc);
    out[mrow * N + n] = acc;
    if (out2) out2[mrow * out2_stride + n] = acc;
    if (ph) {   // AR prediction split for next step's GEMM (only for N=16 final layer)
        __nv_bfloat16 hi = __float2bfloat16(acc);
        ph[mrow * 64 + n] = hi;
        pl[mrow * 64 + n] = __float2bfloat16(acc - __bfloat162float(hi));
    }
}

extern "C" void kernel_launch(void* const* d_in, const int* in_sizes, int n_in,
                              void* d_out, int out_size) {
    const float* x      = (const float*)d_in[0];
    const float* kernel = (const float*)d_in[1];
    const float* rec    = (const float*)d_in[2];
    const float* bias   = (const float*)d_in[3];
    const float* period = (const float*)d_in[4];
    const float* phase  = (const float*)d_in[5];
    const float* ratio  = (const float*)d_in[6];
    const float* w1 = (const float*)d_in[7];  const float* b1 = (const float*)d_in[8];
    const float* w2 = (const float*)d_in[9];  const float* b2 = (const float*)d_in[10];
    const float* w3 = (const float*)d_in[11]; const float* b3 = (const float*)d_in[12];
    const float* wo = (const float*)d_in[13]; const float* bo = (const float*)d_in[14];
    float* out = (float*)d_out;

    const int T = in_sizes[0] / (BATCH * FEATS);   // 512

    float *hb, *cb, *pb, *d1, *d2, *d3;
    __nv_bfloat16 *ahb, *alb, *xhb, *xlb, *phb, *plb;
    unsigned char *mkb;
    cudaGetSymbolAddress((void**)&hb,  g_h);
    cudaGetSymbolAddress((void**)&cb,  g_c);
    cudaGetSymbolAddress((void**)&pb,  g_p);
    cudaGetSymbolAddress((void**)&d1,  g_d1);
    cudaGetSymbolAddress((void**)&d2,  g_d2);
    cudaGetSymbolAddress((void**)&d3,  g_d3);
    cudaGetSymbolAddress((void**)&ahb, g_Ah);
    cudaGetSymbolAddress((void**)&alb, g_Al);
    cudaGetSymbolAddress((void**)&xhb, g_xh);
    cudaGetSymbolAddress((void**)&xlb, g_xl);
    cudaGetSymbolAddress((void**)&phb, g_ph);
    cudaGetSymbolAddress((void**)&plb, g_pl);
    cudaGetSymbolAddress((void**)&mkb, g_mask);

    cudaFuncSetAttribute(step_mma, cudaFuncAttributeMaxDynamicSharedMemorySize, SMEM_DYN);

    init_zero<<<512, 256>>>();
    prep_B<<<4096, 256>>>(rec, kernel, bias);
    prep_X<<<4096, 256>>>(x, T);
    prep_mask<<<512, 256>>>(x, T);

    const dim3 sgrid(BATCH / 64, WCOLS / 128);   // (4, 32)
    const int SU = BATCH * UNITS;
    int par = 0;

    // warm phase: T masked steps
    for (int t = 0; t < T; t++) {
        step_mma<<<sgrid, 256, SMEM_DYN>>>(
            ahb + par * SU, alb + par * SU,
            xhb + t * BATCH * 64, xlb + t * BATCH * 64,
            x + t * FEATS, T * FEATS, mkb + t * BATCH,
            hb + par * SU, cb + par * SU,
            hb + (par ^ 1) * SU, cb + (par ^ 1) * SU,
            ahb + (par ^ 1) * SU, alb + (par ^ 1) * SU,
            period, phase, ratio);
        par ^= 1;
    }

    // dense stack: h -> d1 -> d2 -> d3 -> (p, out[:,s,:], p hi/lo)
    auto dense_stack = [&](int s) {
        const float* h = hb + par * SU;
        dense_kernel<<<dim3(16,16), dim3(16,16)>>>(h,  UNITS, w1, 256, b1, d1, 1, nullptr, 0, nullptr, nullptr);
        dense_kernel<<<dim3(16, 8), dim3(16,16)>>>(d1, 256,   w2, 128, b2, d2, 1, nullptr, 0, nullptr, nullptr);
        dense_kernel<<<dim3(16, 4), dim3(16,16)>>>(d2, 128,   w3, 64,  b3, d3, 1, nullptr, 0, nullptr, nullptr);
        dense_kernel<<<dim3(16, 1), dim3(16,16)>>>(d3, 64,    wo, FEATS, bo, pb, 0,
                                                   out + s * FEATS, OUTSTEPS * FEATS, phb, plb);
    };

    dense_stack(0);   // pred0

    // autoregressive phase: 23 unmasked steps fed by p
    for (int s = 1; s < OUTSTEPS; s++) {
        step_mma<<<sgrid, 256, SMEM_DYN>>>(
            ahb + par * SU, alb + par * SU,
            phb, plb,
            pb, FEATS, nullptr,
            hb + par * SU, cb + par * SU,
            hb + (par ^ 1) * SU, cb + (par ^ 1) * SU,
            ahb + (par ^ 1) * SU, alb + (par ^ 1) * SU,
            period, phase, ratio);
        par ^= 1;
        dense_stack(s);
    }
}

// round 15
// speedup vs baseline: 4.8711x; 1.1954x over previous
#include <cuda_runtime.h>
#include <cuda_fp16.h>
#include <cstdint>

// Problem constants (shapes fixed by setup_inputs)
#define BATCH 256
#define UNITS 1024
#define FEATS 16
#define WCOLS 4096          // 4*UNITS
#define OUTSTEPS 24
#define LEAKF 0.001f
#define MASKV (-1.0f)
#define TSTEPS 512
#define KPAD 1088           // 1024 (h) + 64 (x chunk, zero-padded past 16)
#define CHUNKS 17           // K-chunks of 64 (last one: only 16 real cols)
#define BUFBYTES 40960      // A 8K + Bh 16K + Bl 16K per stage
#define NSTAGE 4            // cp.async ring depth

#define SMEM_DBUF (NSTAGE * BUFBYTES)            // 163840
#define SMEM_HSTAGE SMEM_DBUF                    // hin stage: 64 rows * 36 floats
#define SMEM_CSTAGE (SMEM_DBUF + 9216)           // cin stage
#define SMEM_DYN (SMEM_DBUF + 2 * 9216 + 1024)   // 183296

typedef unsigned int u32;
typedef unsigned long long u64;

// -------- device scratch (no allocation allowed) --------
__device__ __align__(256) float g_h[2][BATCH * UNITS];
__device__ __align__(256) float g_c[2][BATCH * UNITS];
__device__ __align__(256) __half g_A[2][BATCH * UNITS];    // h in fp16, per parity (A operand)
__device__ __align__(256) __half g_Bh[WCOLS * KPAD];       // weights hi fp16, rows n=4u+g, K-contig
__device__ __align__(256) __half g_Bl[WCOLS * KPAD];       // weights lo fp16 (residual)
__device__ __align__(256) __half g_x16[TSTEPS * BATCH * 64];// x fp16, padded to 64 cols
__device__ unsigned char g_mask[TSTEPS * BATCH];
__device__ __align__(256) float g_br[WCOLS];               // gate-interleaved bias
__device__ __align__(256) float g_p[BATCH * FEATS];
__device__ __align__(256) __half g_p16[BATCH * 64];        // AR prediction fp16 (padded)
__device__ __align__(256) float g_d1[BATCH * 256];
__device__ __align__(256) float g_d2[BATCH * 128];
__device__ __align__(256) float g_d3[BATCH * 64];

// ---------------- PTX helpers (sm_80+ features only) ----------------
__device__ __forceinline__ u32 su32(const void* p) {
    return (u32)__cvta_generic_to_shared(p);
}
__device__ __forceinline__ void cpasync16(u32 dst, const void* src) {
    asm volatile("cp.async.cg.shared.global [%0], [%1], 16;" :: "r"(dst), "l"(src) : "memory");
}
#define CP_COMMIT() asm volatile("cp.async.commit_group;" ::: "memory")
#define CP_WAIT_2() asm volatile("cp.async.wait_group 2;" ::: "memory")

__device__ __forceinline__ void ldsm4(u32& r0, u32& r1, u32& r2, u32& r3, u32 addr) {
    asm volatile("ldmatrix.sync.aligned.m8n8.x4.shared.b16 {%0,%1,%2,%3}, [%4];"
                 : "=r"(r0), "=r"(r1), "=r"(r2), "=r"(r3) : "r"(addr));
}
__device__ __forceinline__ void hmma(float* d, const u32* a, const u32* b) {
    asm("mma.sync.aligned.m16n8k16.row.col.f32.f16.f16.f32 "
        "{%0,%1,%2,%3}, {%4,%5,%6,%7}, {%8,%9}, {%0,%1,%2,%3};"
        : "+f"(d[0]), "+f"(d[1]), "+f"(d[2]), "+f"(d[3])
        : "r"(a[0]), "r"(a[1]), "r"(a[2]), "r"(a[3]), "r"(b[0]), "r"(b[1]));
}

// ---------------- prep kernels ----------------
__global__ void init_zero() {
    for (int i = blockIdx.x * blockDim.x + threadIdx.x;
         i < BATCH * UNITS; i += gridDim.x * blockDim.x) {
        g_h[0][i] = 0.f; g_h[1][i] = 0.f;
        g_c[0][i] = 0.f; g_c[1][i] = 0.f;
        g_A[0][i] = __float2half(0.f); g_A[1][i] = __float2half(0.f);
        if (i < BATCH * 64) g_p16[i] = __float2half(0.f);
    }
}

// B[n][k], n = 4u+g (gate-interleaved), k<1024: rec; 1024<=k<1040: input kernel; else 0
__global__ void prep_B(const float* __restrict__ rec, const float* __restrict__ ker,
                       const float* __restrict__ bias) {
    for (int i = blockIdx.x * blockDim.x + threadIdx.x;
         i < WCOLS * KPAD; i += gridDim.x * blockDim.x) {
        int n = i / KPAD, k = i - n * KPAD;
        int u = n >> 2, g = n & 3;
        float w = 0.f;
        if (k < UNITS) w = rec[k * WCOLS + g * UNITS + u];
        else if (k < UNITS + FEATS) w = ker[(k - UNITS) * WCOLS + g * UNITS + u];
        __half hi = __float2half(w);
        g_Bh[i] = hi;
        g_Bl[i] = __float2half(w - __half2float(hi));
        if (k == 0) g_br[n] = bias[g * UNITS + u];
    }
}

// x fp16, padded to 64 cols: g_x16[t][row][c]
__global__ void prep_X(const float* __restrict__ x, int T) {
    for (int i = blockIdx.x * blockDim.x + threadIdx.x;
         i < T * BATCH * 64; i += gridDim.x * blockDim.x) {
        int t = i / (BATCH * 64);
        int r = (i / 64) % BATCH;
        int c = i % 64;
        float v = (c < FEATS) ? x[(r * T + t) * FEATS + c] : 0.f;
        g_x16[i] = __float2half(v);
    }
}

__global__ void prep_mask(const float* __restrict__ x, int T) {
    for (int i = blockIdx.x * blockDim.x + threadIdx.x;
         i < T * BATCH; i += gridDim.x * blockDim.x) {
        int t = i / BATCH, r = i % BATCH;
        int m = 0;
        for (int f = 0; f < FEATS; f++)
            if (x[(r * T + t) * FEATS + f] != MASKV) m = 1;
        g_mask[i] = (unsigned char)m;
    }
}

// ---------------- mma.sync PLSTM step ----------------
// grid (4, 32): CTA = 64 batch rows x 128 gate-cols, 8 warps of 32x32 (2M x 4N).
// K = 16 chunks of 64 (recurrent) + 1 chunk of 16 (x features).
// fp16 2-pass: A single fp16, B split hi/lo fp16; z = A*Bh + A*Bl (fp32 accum).
// 4-stage cp.async ring, prefetch distance 2, one __syncthreads per chunk.
__global__ void __launch_bounds__(256)
step_mma(const __half* __restrict__ Aop, const __half* __restrict__ Xop,
         const float* __restrict__ tsrc, int tstride, const unsigned char* __restrict__ msk,
         const float* __restrict__ hin, const float* __restrict__ cin,
         float* __restrict__ hout, float* __restrict__ cout,
         __half* __restrict__ AO,
         const float* __restrict__ period, const float* __restrict__ phase,
         const float* __restrict__ ratio)
{
    extern __shared__ char dsm_raw[];
    char* dsm = (char*)((((uintptr_t)dsm_raw) + 1023) & ~(uintptr_t)1023);
    const u32 dynb = su32(dsm);

    const int tid  = threadIdx.x;
    const int lane = tid & 31, wid = tid >> 5;
    const int warpM = wid & 1, warpN = wid >> 1;     // 2 M-warps x 4 N-warps
    const int m0 = blockIdx.x * 64;
    const int n0 = blockIdx.y * 128;
    const int u0 = n0 >> 2;

    float* s_hin = (float*)(dsm + SMEM_HSTAGE);      // [64][36] padded
    float* s_cin = (float*)(dsm + SMEM_CSTAGE);

    float acc[2][4][4];
    #pragma unroll
    for (int a = 0; a < 2; a++)
        #pragma unroll
        for (int b = 0; b < 4; b++)
            #pragma unroll
            for (int d = 0; d < 4; d++) acc[a][b][d] = 0.f;

    // ldmatrix per-lane geometry
    const int aRowB = warpM * 32 + (lane & 7) + (((lane >> 3) & 1) << 3); // + mt*16
    const int acol  = lane >> 4;                                          // k8 half
    const int bRowB = warpN * 32 + (lane & 7) + ((lane >> 4) << 3);       // + p*16
    const int bcol  = (lane >> 3) & 1;                                    // k8 half

    // fill chunk c into smem stage (c % NSTAGE) via cp.async
    // stage layout: A @0 (8KB), Bh @8192 (16KB), Bl @24576 (16KB)
    auto fill = [&](int c) {
        const u32 sb = dynb + (c & (NSTAGE - 1)) * BUFBYTES;
        if (c < 16) {
            const int kb = c * 64;
            #pragma unroll
            for (int q = 0; q < 2; q++) {           // A: 64 rows x 8 chunks
                int ci = tid + q * 256;
                int row = ci >> 3, cc = ci & 7;
                u32 d = (u32)row * 128 + (u32)((cc ^ (row & 7)) << 4);
                cpasync16(sb + d, Aop + (m0 + row) * UNITS + kb + cc * 8);
            }
            #pragma unroll
            for (int q = 0; q < 4; q++) {           // B: 128 rows x 8 chunks, hi+lo
                int ci = tid + q * 256;
                int row = ci >> 3, cc = ci & 7;
                u32 d = (u32)row * 128 + (u32)((cc ^ (row & 7)) << 4);
                cpasync16(sb + 8192 + d,  g_Bh + (n0 + row) * KPAD + kb + cc * 8);
                cpasync16(sb + 24576 + d, g_Bl + (n0 + row) * KPAD + kb + cc * 8);
            }
        } else {
            // x chunk: only first 16 K-cols are real (2 chunks of 8 fp16)
            if (tid < 128) {                        // A: 64 rows x 2 chunks
                int row = tid >> 1, cc = tid & 1;
                u32 d = (u32)row * 128 + (u32)((cc ^ (row & 7)) << 4);
                cpasync16(sb + d, Xop + (m0 + row) * 64 + cc * 8);
            }
            {                                        // B: 128 rows x 2 chunks, hi+lo
                int row = tid >> 1, cc = tid & 1;
                u32 d = (u32)row * 128 + (u32)((cc ^ (row & 7)) << 4);
                cpasync16(sb + 8192 + d,  g_Bh + (n0 + row) * KPAD + 1024 + cc * 8);
                cpasync16(sb + 24576 + d, g_Bl + (n0 + row) * KPAD + 1024 + cc * 8);
            }
        }
    };

    auto computeKs = [&](u32 sb, int ks) {
        u32 af[2][4], bhf[4][2], blf[4][2];
        #pragma unroll
        for (int mt = 0; mt < 2; mt++) {
            int r = aRowB + mt * 16;
            int ch = ks * 2 + acol;
            u32 ad = sb + (u32)r * 128 + (u32)((ch ^ (r & 7)) << 4);
            ldsm4(af[mt][0], af[mt][1], af[mt][2], af[mt][3], ad);
        }
        #pragma unroll
        for (int p = 0; p < 2; p++) {
            int r = bRowB + p * 16;
            int ch = ks * 2 + bcol;
            u32 bd = sb + 8192 + (u32)r * 128 + (u32)((ch ^ (r & 7)) << 4);
            u32 r0, r1, r2, r3;
            ldsm4(r0, r1, r2, r3, bd);
            bhf[2 * p][0] = r0; bhf[2 * p][1] = r1;
            bhf[2 * p + 1][0] = r2; bhf[2 * p + 1][1] = r3;
            ldsm4(r0, r1, r2, r3, bd + 16384);
            blf[2 * p][0] = r0; blf[2 * p][1] = r1;
            blf[2 * p + 1][0] = r2; blf[2 * p + 1][1] = r3;
        }
        #pragma unroll
        for (int mt = 0; mt < 2; mt++)
            #pragma unroll
            for (int nt = 0; nt < 4; nt++) {
                hmma(acc[mt][nt], af[mt], bhf[nt]);   // A*Bh
                hmma(acc[mt][nt], af[mt], blf[nt]);   // A*Bl
            }
    };

    // ---- prologue: fill(0), fill(1) + h/c state prefetch ----
    fill(0);
    CP_COMMIT();                       // group 0
    fill(1);
    #pragma unroll
    for (int q = 0; q < 2; q++) {      // h/c state (needed only at epilogue)
        int ci = tid + q * 256;        // 64 rows x 8 chunks of 4 floats
        int row = ci >> 3, c4 = ci & 7;
        cpasync16(dynb + SMEM_HSTAGE + (u32)(row * 36 + c4 * 4) * 4,
                  hin + (m0 + row) * UNITS + u0 + c4 * 4);
        cpasync16(dynb + SMEM_CSTAGE + (u32)(row * 36 + c4 * 4) * 4,
                  cin + (m0 + row) * UNITS + u0 + c4 * 4);
    }
    CP_COMMIT();                       // group 1 (fill 1 + state)

    // ---- main loop: one barrier per chunk ----
    #pragma unroll 1
    for (int c = 0; c < CHUNKS; c++) {
        if (c + 2 < CHUNKS) fill(c + 2);
        CP_COMMIT();                   // group c+2 (possibly empty at tail)
        CP_WAIT_2();                   // own groups through c complete
        __syncthreads();               // cross-thread visibility + stage-reuse safety
        const u32 sb = dynb + (c & (NSTAGE - 1)) * BUFBYTES;
        if (c < 16) {
            #pragma unroll
            for (int ks = 0; ks < 4; ks++) computeKs(sb, ks);
        } else {
            computeKs(sb, 0);
        }
    }
    __syncthreads();                   // all computes done before staging epilogue

    // ---- epilogue: gates + phased time-gate, staged via smem ----
    float* s_oh = (float*)(dsm + 0);                 // [64][33]
    float* s_oc = (float*)(dsm + 8448);              // [64][33]
    __half* s_a = (__half*)(dsm + 16896);            // [64][33]

    #pragma unroll
    for (int mt = 0; mt < 2; mt++) {
        #pragma unroll
        for (int nt = 0; nt < 4; nt++) {
            float d0 = acc[mt][nt][0], d1 = acc[mt][nt][1];
            float d2 = acc[mt][nt][2], d3 = acc[mt][nt][3];
            float v0 = __shfl_xor_sync(0xFFFFFFFFu, d0, 1);
            float v1 = __shfl_xor_sync(0xFFFFFFFFu, d1, 1);
            float v2 = __shfl_xor_sync(0xFFFFFFFFu, d2, 1);
            float v3 = __shfl_xor_sync(0xFFFFFFFFu, d3, 1);
            int odd = lane & 1;
            float zi = odd ? v2 : d0;
            float zf = odd ? v3 : d1;
            float zg = odd ? d2 : v0;
            float zo = odd ? d3 : v1;
            int rr = warpM * 32 + mt * 16 + (lane >> 2) + (odd ? 8 : 0);
            int colL = warpN * 32 + nt * 8 + ((lane & 2) ? 4 : 0);  // CTA-local gate col
            int cu = colL >> 2;                                      // CTA-local unit
            int u = u0 + cu;                                         // global unit
            float4 bb = *(const float4*)(g_br + n0 + colL);
            zi += bb.x; zf += bb.y; zg += bb.z; zo += bb.w;

            float ig = 1.f / (1.f + expf(-zi));
            float fg = 1.f / (1.f + expf(-zf));
            float gg = tanhf(zg);
            float og = 1.f / (1.f + expf(-zo));
            float ho = s_hin[rr * 36 + cu], co = s_cin[rr * 36 + cu];
            float nc = fg * co + ig * gg;
            float nh = og * tanhf(nc);
            int grow = m0 + rr;
            float tval = tsrc[grow * tstride];
            float per = period[u], pha = phase[u], ro = ratio[u];
            float cr = fmodf(tval - pha, per);
            if (cr < 0.f) cr += per;
            cr /= per;
            float kg;
            if (cr < 0.5f * ro)      kg = 2.f * cr / ro;
            else if (cr < ro)        kg = 2.f - 2.f * cr / ro;
            else                     kg = LEAKF * cr;
            float h2 = kg * nh + (1.f - kg) * ho;
            float c2 = kg * nc + (1.f - kg) * co;
            if (msk && !msk[grow]) { h2 = ho; c2 = co; }
            s_oh[rr * 33 + cu] = h2;
            s_oc[rr * 33 + cu] = c2;
            s_a[rr * 33 + cu]  = __float2half(h2);
        }
    }
    __syncthreads();

    // coalesced writeback: 64 rows x 32 units per CTA
    #pragma unroll
    for (int q = 0; q < 8; q++) {
        int idx = tid + q * 256;             // 0..2047
        int row = idx >> 5, cu = idx & 31;
        int gidx = (m0 + row) * UNITS + u0 + cu;
        hout[gidx] = s_oh[row * 33 + cu];
        cout[gidx] = s_oc[row * 33 + cu];
        AO[gidx]   = s_a[row * 33 + cu];
    }
}

// -------- generic small dense layer: out = act(A[256,K] @ W[K,N] + b) --------
__global__ void __launch_bounds__(256)
dense_kernel(const float* __restrict__ A, int K,
             const float* __restrict__ W, int N,
             const float* __restrict__ bias,
             float* __restrict__ out, int act,
             float* __restrict__ out2, int out2_stride,
             __half* __restrict__ ph)
{
    __shared__ float As[16][16];
    __shared__ float Ws[16][16];
    int tx = threadIdx.x, ty = threadIdx.y;
    int m0 = blockIdx.x * 16, n0 = blockIdx.y * 16;
    float acc = 0.f;
    for (int k0 = 0; k0 < K; k0 += 16) {
        As[ty][tx] = A[(m0 + ty) * K + k0 + tx];
        Ws[ty][tx] = W[(k0 + ty) * N + n0 + tx];
        __syncthreads();
        #pragma unroll
        for (int kk = 0; kk < 16; kk++)
            acc += As[ty][kk] * Ws[kk][tx];
        __syncthreads();
    }
    int n = n0 + tx, mrow = m0 + ty;
    acc += bias[n];
    if (act) acc = tanhf(acc);
    out[mrow * N + n] = acc;
    if (out2) out2[mrow * out2_stride + n] = acc;
    if (ph)   // AR prediction fp16 for next step's GEMM (only for N=16 final layer)
        ph[mrow * 64 + n] = __float2half(acc);
}

extern "C" void kernel_launch(void* const* d_in, const int* in_sizes, int n_in,
                              void* d_out, int out_size) {
    const float* x      = (const float*)d_in[0];
    const float* kernel = (const float*)d_in[1];
    const float* rec    = (const float*)d_in[2];
    const float* bias   = (const float*)d_in[3];
    const float* period = (const float*)d_in[4];
    const float* phase  = (const float*)d_in[5];
    const float* ratio  = (const float*)d_in[6];
    const float* w1 = (const float*)d_in[7];  const float* b1 = (const float*)d_in[8];
    const float* w2 = (const float*)d_in[9];  const float* b2 = (const float*)d_in[10];
    const float* w3 = (const float*)d_in[11]; const float* b3 = (const float*)d_in[12];
    const float* wo = (const float*)d_in[13]; const float* bo = (const float*)d_in[14];
    float* out = (float*)d_out;

    const int T = in_sizes[0] / (BATCH * FEATS);   // 512

    float *hb, *cb, *pb, *d1, *d2, *d3;
    __half *ab, *xb, *p16b;
    unsigned char *mkb;
    cudaGetSymbolAddress((void**)&hb,   g_h);
    cudaGetSymbolAddress((void**)&cb,   g_c);
    cudaGetSymbolAddress((void**)&pb,   g_p);
    cudaGetSymbolAddress((void**)&d1,   g_d1);
    cudaGetSymbolAddress((void**)&d2,   g_d2);
    cudaGetSymbolAddress((void**)&d3,   g_d3);
    cudaGetSymbolAddress((void**)&ab,   g_A);
    cudaGetSymbolAddress((void**)&xb,   g_x16);
    cudaGetSymbolAddress((void**)&p16b, g_p16);
    cudaGetSymbolAddress((void**)&mkb,  g_mask);

    cudaFuncSetAttribute(step_mma, cudaFuncAttributeMaxDynamicSharedMemorySize, SMEM_DYN);

    init_zero<<<512, 256>>>();
    prep_B<<<4096, 256>>>(rec, kernel, bias);
    prep_X<<<4096, 256>>>(x, T);
    prep_mask<<<512, 256>>>(x, T);

    const dim3 sgrid(BATCH / 64, WCOLS / 128);   // (4, 32)
    const int SU = BATCH * UNITS;
    int par = 0;

    // warm phase: T masked steps
    for (int t = 0; t < T; t++) {
        step_mma<<<sgrid, 256, SMEM_DYN>>>(
            ab + par * SU,
            xb + t * BATCH * 64,
            x + t * FEATS, T * FEATS, mkb + t * BATCH,
            hb + par * SU, cb + par * SU,
            hb + (par ^ 1) * SU, cb + (par ^ 1) * SU,
            ab + (par ^ 1) * SU,
            period, phase, ratio);
        par ^= 1;
    }

    // dense stack: h -> d1 -> d2 -> d3 -> (p, out[:,s,:], p fp16)
    auto dense_stack = [&](int s) {
        const float* h = hb + par * SU;
        dense_kernel<<<dim3(16,16), dim3(16,16)>>>(h,  UNITS, w1, 256, b1, d1, 1, nullptr, 0, nullptr);
        dense_kernel<<<dim3(16, 8), dim3(16,16)>>>(d1, 256,   w2, 128, b2, d2, 1, nullptr, 0, nullptr);
        dense_kernel<<<dim3(16, 4), dim3(16,16)>>>(d2, 128,   w3, 64,  b3, d3, 1, nullptr, 0, nullptr);
        dense_kernel<<<dim3(16, 1), dim3(16,16)>>>(d3, 64,    wo, FEATS, bo, pb, 0,
                                                   out + s * FEATS, OUTSTEPS * FEATS, p16b);
    };

    dense_stack(0);   // pred0

    // autoregressive phase: 23 unmasked steps fed by p
    for (int s = 1; s < OUTSTEPS; s++) {
        step_mma<<<sgrid, 256, SMEM_DYN>>>(
            ab + par * SU,
            p16b,
            pb, FEATS, nullptr,
            hb + par * SU, cb + par * SU,
            hb + (par ^ 1) * SU, cb + (par ^ 1) * SU,
            ab + (par ^ 1) * SU,
            period, phase, ratio);
        par ^= 1;
        dense_stack(s);
    }
}

// round 17
// speedup vs baseline: 5.2786x; 1.0837x over previous
#include <cuda_runtime.h>
#include <cuda_fp16.h>
#include <cstdint>

// Problem constants (shapes fixed by setup_inputs)
#define BATCH 256
#define UNITS 1024
#define FEATS 16
#define WCOLS 4096          // 4*UNITS
#define OUTSTEPS 24
#define LEAKF 0.001f
#define MASKV (-1.0f)
#define TSTEPS 512
#define KPAD 1088           // 1024 (h) + 64 (x chunk, zero-padded past 16)
#define CHUNKS 17           // K-chunks of 64 (last one: only 16 real cols)
#define BUFBYTES 40960      // A 8K + Bh 16K + Bl 16K per stage
#define NSTAGE 4            // cp.async ring depth

#define SMEM_DBUF (NSTAGE * BUFBYTES)            // 163840
#define SMEM_HSTAGE SMEM_DBUF                    // hin stage: 64 rows * 36 floats
#define SMEM_CSTAGE (SMEM_DBUF + 9216)           // cin stage
#define SMEM_DYN (SMEM_DBUF + 2 * 9216 + 1024)   // 183296

typedef unsigned int u32;
typedef unsigned long long u64;

// -------- device scratch (no allocation allowed) --------
__device__ __align__(256) float g_h[2][BATCH * UNITS];
__device__ __align__(256) float g_c[2][BATCH * UNITS];
__device__ __align__(256) __half g_A[2][BATCH * UNITS];    // h in fp16, per parity (A operand)
__device__ __align__(256) __half g_Bh[WCOLS * KPAD];       // weights hi fp16, rows n=4u+g, K-contig
__device__ __align__(256) __half g_Bl[WCOLS * KPAD];       // weights lo fp16 (residual)
__device__ __align__(256) __half g_x16[TSTEPS * BATCH * 64];// x fp16, padded to 64 cols
__device__ unsigned char g_mask[TSTEPS * BATCH];
__device__ __align__(256) float g_br[WCOLS];               // gate-interleaved bias
__device__ __align__(256) float g_p[BATCH * FEATS];
__device__ __align__(256) __half g_p16[BATCH * 64];        // AR prediction fp16 (padded)
__device__ __align__(256) float g_d1[BATCH * 256];
__device__ __align__(256) float g_d2[BATCH * 128];
__device__ __align__(256) float g_d3[BATCH * 64];

// ---------------- PTX helpers (sm_80+ features only) ----------------
__device__ __forceinline__ u32 su32(const void* p) {
    return (u32)__cvta_generic_to_shared(p);
}
__device__ __forceinline__ void cpasync16(u32 dst, const void* src) {
    asm volatile("cp.async.cg.shared.global [%0], [%1], 16;" :: "r"(dst), "l"(src) : "memory");
}
#define CP_COMMIT() asm volatile("cp.async.commit_group;" ::: "memory")
#define CP_WAIT_2() asm volatile("cp.async.wait_group 2;" ::: "memory")

__device__ __forceinline__ void ldsm4(u32& r0, u32& r1, u32& r2, u32& r3, u32 addr) {
    asm volatile("ldmatrix.sync.aligned.m8n8.x4.shared.b16 {%0,%1,%2,%3}, [%4];"
                 : "=r"(r0), "=r"(r1), "=r"(r2), "=r"(r3) : "r"(addr));
}
__device__ __forceinline__ void hmma(float* d, const u32* a, const u32* b) {
    asm("mma.sync.aligned.m16n8k16.row.col.f32.f16.f16.f32 "
        "{%0,%1,%2,%3}, {%4,%5,%6,%7}, {%8,%9}, {%0,%1,%2,%3};"
        : "+f"(d[0]), "+f"(d[1]), "+f"(d[2]), "+f"(d[3])
        : "r"(a[0]), "r"(a[1]), "r"(a[2]), "r"(a[3]), "r"(b[0]), "r"(b[1]));
}

// fast transcendentals (MUFU-based; error ~1e-6, negligible vs 2.5e-4 budget)
__device__ __forceinline__ float fsig(float z) {
    return __fdividef(1.f, 1.f + __expf(-z));
}
__device__ __forceinline__ float ftanh(float z) {
    float a = fabsf(z);
    float e = __expf(-2.f * a);
    float t = __fdividef(1.f - e, 1.f + e);
    return copysignf(t, z);
}

// ---------------- prep kernels ----------------
__global__ void init_zero() {
    for (int i = blockIdx.x * blockDim.x + threadIdx.x;
         i < BATCH * UNITS; i += gridDim.x * blockDim.x) {
        g_h[0][i] = 0.f; g_h[1][i] = 0.f;
        g_c[0][i] = 0.f; g_c[1][i] = 0.f;
        g_A[0][i] = __float2half(0.f); g_A[1][i] = __float2half(0.f);
        if (i < BATCH * 64) g_p16[i] = __float2half(0.f);
    }
}

// B[n][k], n = 4u+g (gate-interleaved), k<1024: rec; 1024<=k<1040: input kernel; else 0
__global__ void prep_B(const float* __restrict__ rec, const float* __restrict__ ker,
                       const float* __restrict__ bias) {
    for (int i = blockIdx.x * blockDim.x + threadIdx.x;
         i < WCOLS * KPAD; i += gridDim.x * blockDim.x) {
        int n = i / KPAD, k = i - n * KPAD;
        int u = n >> 2, g = n & 3;
        float w = 0.f;
        if (k < UNITS) w = rec[k * WCOLS + g * UNITS + u];
        else if (k < UNITS + FEATS) w = ker[(k - UNITS) * WCOLS + g * UNITS + u];
        __half hi = __float2half(w);
        g_Bh[i] = hi;
        g_Bl[i] = __float2half(w - __half2float(hi));
        if (k == 0) g_br[n] = bias[g * UNITS + u];
    }
}

// x fp16, padded to 64 cols: g_x16[t][row][c]
__global__ void prep_X(const float* __restrict__ x, int T) {
    for (int i = blockIdx.x * blockDim.x + threadIdx.x;
         i < T * BATCH * 64; i += gridDim.x * blockDim.x) {
        int t = i / (BATCH * 64);
        int r = (i / 64) % BATCH;
        int c = i % 64;
        float v = (c < FEATS) ? x[(r * T + t) * FEATS + c] : 0.f;
        g_x16[i] = __float2half(v);
    }
}

__global__ void prep_mask(const float* __restrict__ x, int T) {
    for (int i = blockIdx.x * blockDim.x + threadIdx.x;
         i < T * BATCH; i += gridDim.x * blockDim.x) {
        int t = i / BATCH, r = i % BATCH;
        int m = 0;
        for (int f = 0; f < FEATS; f++)
            if (x[(r * T + t) * FEATS + f] != MASKV) m = 1;
        g_mask[i] = (unsigned char)m;
    }
}

// ---------------- mma.sync PLSTM step ----------------
// grid (4, 32): CTA = 64 batch rows x 128 gate-cols, 8 warps of 32x32 (2M x 4N).
// K = 16 chunks of 64 (recurrent) + 1 chunk of 16 (x features).
// fp16 2-pass: A single fp16, B split hi/lo fp16; z = A*Bh + A*Bl (fp32 accum).
// 4-stage cp.async ring, prefetch distance 2, one __syncthreads per chunk.
__global__ void __launch_bounds__(256)
step_mma(const __half* __restrict__ Aop, const __half* __restrict__ Xop,
         const float* __restrict__ tsrc, int tstride, const unsigned char* __restrict__ msk,
         const float* __restrict__ hin, const float* __restrict__ cin,
         float* __restrict__ hout, float* __restrict__ cout,
         __half* __restrict__ AO,
         const float* __restrict__ period, const float* __restrict__ phase,
         const float* __restrict__ ratio)
{
    extern __shared__ char dsm_raw[];
    char* dsm = (char*)((((uintptr_t)dsm_raw) + 1023) & ~(uintptr_t)1023);
    const u32 dynb = su32(dsm);

    const int tid  = threadIdx.x;
    const int lane = tid & 31, wid = tid >> 5;
    const int warpM = wid & 1, warpN = wid >> 1;     // 2 M-warps x 4 N-warps
    const int m0 = blockIdx.x * 64;
    const int n0 = blockIdx.y * 128;
    const int u0 = n0 >> 2;

    float* s_hin = (float*)(dsm + SMEM_HSTAGE);      // [64][36] padded
    float* s_cin = (float*)(dsm + SMEM_CSTAGE);

    float acc[2][4][4];
    #pragma unroll
    for (int a = 0; a < 2; a++)
        #pragma unroll
        for (int b = 0; b < 4; b++)
            #pragma unroll
            for (int d = 0; d < 4; d++) acc[a][b][d] = 0.f;

    // ldmatrix per-lane geometry
    const int aRowB = warpM * 32 + (lane & 7) + (((lane >> 3) & 1) << 3); // + mt*16
    const int acol  = lane >> 4;                                          // k8 half
    const int bRowB = warpN * 32 + (lane & 7) + ((lane >> 4) << 3);       // + p*16
    const int bcol  = (lane >> 3) & 1;                                    // k8 half

    // fill chunk c into smem stage (c % NSTAGE) via cp.async
    // stage layout: A @0 (8KB), Bh @8192 (16KB), Bl @24576 (16KB)
    auto fill = [&](int c) {
        const u32 sb = dynb + (c & (NSTAGE - 1)) * BUFBYTES;
        if (c < 16) {
            const int kb = c * 64;
            #pragma unroll
            for (int q = 0; q < 2; q++) {           // A: 64 rows x 8 chunks
                int ci = tid + q * 256;
                int row = ci >> 3, cc = ci & 7;
                u32 d = (u32)row * 128 + (u32)((cc ^ (row & 7)) << 4);
                cpasync16(sb + d, Aop + (m0 + row) * UNITS + kb + cc * 8);
            }
            #pragma unroll
            for (int q = 0; q < 4; q++) {           // B: 128 rows x 8 chunks, hi+lo
                int ci = tid + q * 256;
                int row = ci >> 3, cc = ci & 7;
                u32 d = (u32)row * 128 + (u32)((cc ^ (row & 7)) << 4);
                cpasync16(sb + 8192 + d,  g_Bh + (n0 + row) * KPAD + kb + cc * 8);
                cpasync16(sb + 24576 + d, g_Bl + (n0 + row) * KPAD + kb + cc * 8);
            }
        } else {
            // x chunk: only first 16 K-cols are real (2 chunks of 8 fp16)
            if (tid < 128) {                        // A: 64 rows x 2 chunks
                int row = tid >> 1, cc = tid & 1;
                u32 d = (u32)row * 128 + (u32)((cc ^ (row & 7)) << 4);
                cpasync16(sb + d, Xop + (m0 + row) * 64 + cc * 8);
            }
            {                                        // B: 128 rows x 2 chunks, hi+lo
                int row = tid >> 1, cc = tid & 1;
                u32 d = (u32)row * 128 + (u32)((cc ^ (row & 7)) << 4);
                cpasync16(sb + 8192 + d,  g_Bh + (n0 + row) * KPAD + 1024 + cc * 8);
                cpasync16(sb + 24576 + d, g_Bl + (n0 + row) * KPAD + 1024 + cc * 8);
            }
        }
    };

    auto computeKs = [&](u32 sb, int ks) {
        u32 af[2][4], bhf[4][2], blf[4][2];
        #pragma unroll
        for (int mt = 0; mt < 2; mt++) {
            int r = aRowB + mt * 16;
            int ch = ks * 2 + acol;
            u32 ad = sb + (u32)r * 128 + (u32)((ch ^ (r & 7)) << 4);
            ldsm4(af[mt][0], af[mt][1], af[mt][2], af[mt][3], ad);
        }
        #pragma unroll
        for (int p = 0; p < 2; p++) {
            int r = bRowB + p * 16;
            int ch = ks * 2 + bcol;
            u32 bd = sb + 8192 + (u32)r * 128 + (u32)((ch ^ (r & 7)) << 4);
            u32 r0, r1, r2, r3;
            ldsm4(r0, r1, r2, r3, bd);
            bhf[2 * p][0] = r0; bhf[2 * p][1] = r1;
            bhf[2 * p + 1][0] = r2; bhf[2 * p + 1][1] = r3;
            ldsm4(r0, r1, r2, r3, bd + 16384);
            blf[2 * p][0] = r0; blf[2 * p][1] = r1;
            blf[2 * p + 1][0] = r2; blf[2 * p + 1][1] = r3;
        }
        #pragma unroll
        for (int mt = 0; mt < 2; mt++)
            #pragma unroll
            for (int nt = 0; nt < 4; nt++) {
                hmma(acc[mt][nt], af[mt], bhf[nt]);   // A*Bh
                hmma(acc[mt][nt], af[mt], blf[nt]);   // A*Bl
            }
    };

    // ---- prologue: fill(0), fill(1) + h/c state prefetch ----
    fill(0);
    CP_COMMIT();                       // group 0
    fill(1);
    #pragma unroll
    for (int q = 0; q < 2; q++) {      // h/c state (needed only at epilogue)
        int ci = tid + q * 256;        // 64 rows x 8 chunks of 4 floats
        int row = ci >> 3, c4 = ci & 7;
        cpasync16(dynb + SMEM_HSTAGE + (u32)(row * 36 + c4 * 4) * 4,
                  hin + (m0 + row) * UNITS + u0 + c4 * 4);
        cpasync16(dynb + SMEM_CSTAGE + (u32)(row * 36 + c4 * 4) * 4,
                  cin + (m0 + row) * UNITS + u0 + c4 * 4);
    }
    CP_COMMIT();                       // group 1 (fill 1 + state)

    // ---- main loop: one barrier per chunk ----
    #pragma unroll 1
    for (int c = 0; c < CHUNKS; c++) {
        if (c + 2 < CHUNKS) fill(c + 2);
        CP_COMMIT();                   // group c+2 (possibly empty at tail)
        CP_WAIT_2();                   // own groups through c complete
        __syncthreads();               // cross-thread visibility + stage-reuse safety
        const u32 sb = dynb + (c & (NSTAGE - 1)) * BUFBYTES;
        if (c < 16) {
            #pragma unroll
            for (int ks = 0; ks < 4; ks++) computeKs(sb, ks);
        } else {
            computeKs(sb, 0);
        }
    }
    __syncthreads();                   // all computes done before staging epilogue

    // ---- epilogue: gates + phased time-gate (fast-math), staged via smem ----
    float* s_oh = (float*)(dsm + 0);                 // [64][33]
    float* s_oc = (float*)(dsm + 8448);              // [64][33]
    __half* s_a = (__half*)(dsm + 16896);            // [64][33]

    #pragma unroll
    for (int mt = 0; mt < 2; mt++) {
        #pragma unroll
        for (int nt = 0; nt < 4; nt++) {
            float d0 = acc[mt][nt][0], d1 = acc[mt][nt][1];
            float d2 = acc[mt][nt][2], d3 = acc[mt][nt][3];
            float v0 = __shfl_xor_sync(0xFFFFFFFFu, d0, 1);
            float v1 = __shfl_xor_sync(0xFFFFFFFFu, d1, 1);
            float v2 = __shfl_xor_sync(0xFFFFFFFFu, d2, 1);
            float v3 = __shfl_xor_sync(0xFFFFFFFFu, d3, 1);
            int odd = lane & 1;
            float zi = odd ? v2 : d0;
            float zf = odd ? v3 : d1;
            float zg = odd ? d2 : v0;
            float zo = odd ? d3 : v1;
            int rr = warpM * 32 + mt * 16 + (lane >> 2) + (odd ? 8 : 0);
            int colL = warpN * 32 + nt * 8 + ((lane & 2) ? 4 : 0);  // CTA-local gate col
            int cu = colL >> 2;                                      // CTA-local unit
            int u = u0 + cu;                                         // global unit
            float4 bb = *(const float4*)(g_br + n0 + colL);
            zi += bb.x; zf += bb.y; zg += bb.z; zo += bb.w;

            float ig = fsig(zi);
            float fg = fsig(zf);
            float gg = ftanh(zg);
            float og = fsig(zo);
            float ho = s_hin[rr * 36 + cu], co = s_cin[rr * 36 + cu];
            float nc = fg * co + ig * gg;
            float nh = og * ftanh(nc);
            int grow = m0 + rr;
            float tval = tsrc[grow * tstride];
            float per = period[u], pha = phase[u], ro = ratio[u];
            // mod(t - pha, per)/per == q - floor(q), q = (t - pha)/per
            float q = __fdividef(tval - pha, per);
            float cr = q - floorf(q);
            float kg;
            if (cr < 0.5f * ro)      kg = 2.f * cr / ro;
            else if (cr < ro)        kg = 2.f - 2.f * cr / ro;
            else                     kg = LEAKF * cr;
            float h2 = kg * nh + (1.f - kg) * ho;
            float c2 = kg * nc + (1.f - kg) * co;
            if (msk && !msk[grow]) { h2 = ho; c2 = co; }
            s_oh[rr * 33 + cu] = h2;
            s_oc[rr * 33 + cu] = c2;
            s_a[rr * 33 + cu]  = __float2half(h2);
        }
    }
    __syncthreads();

    // coalesced writeback: 64 rows x 32 units per CTA
    #pragma unroll
    for (int q = 0; q < 8; q++) {
        int idx = tid + q * 256;             // 0..2047
        int row = idx >> 5, cu = idx & 31;
        int gidx = (m0 + row) * UNITS + u0 + cu;
        hout[gidx] = s_oh[row * 33 + cu];
        cout[gidx] = s_oc[row * 33 + cu];
        AO[gidx]   = s_a[row * 33 + cu];
    }
}

// -------- generic small dense layer: out = act(A[256,K] @ W[K,N] + b) --------
__global__ void __launch_bounds__(256)
dense_kernel(const float* __restrict__ A, int K,
             const float* __restrict__ W, int N,
             const float* __restrict__ bias,
             float* __restrict__ out, int act,
             float* __restrict__ out2, int out2_stride,
             __half* __restrict__ ph)
{
    __shared__ float As[16][16];
    __shared__ float Ws[16][16];
    int tx = threadIdx.x, ty = threadIdx.y;
    int m0 = blockIdx.x * 16, n0 = blockIdx.y * 16;
    float acc = 0.f;
    for (int k0 = 0; k0 < K; k0 += 16) {
        As[ty][tx] = A[(m0 + ty) * K + k0 + tx];
        Ws[ty][tx] = W[(k0 + ty) * N + n0 + tx];
        __syncthreads();
        #pragma unroll
        for (int kk = 0; kk < 16; kk++)
            acc += As[ty][kk] * Ws[kk][tx];
        __syncthreads();
    }
    int n = n0 + tx, mrow = m0 + ty;
    acc += bias[n];
    if (act) acc = tanhf(acc);
    out[mrow * N + n] = acc;
    if (out2) out2[mrow * out2_stride + n] = acc;
    if (ph)   // AR prediction fp16 for next step's GEMM (only for N=16 final layer)
        ph[mrow * 64 + n] = __float2half(acc);
}

extern "C" void kernel_launch(void* const* d_in, const int* in_sizes, int n_in,
                              void* d_out, int out_size) {
    const float* x      = (const float*)d_in[0];
    const float* kernel = (const float*)d_in[1];
    const float* rec    = (const float*)d_in[2];
    const float* bias   = (const float*)d_in[3];
    const float* period = (const float*)d_in[4];
    const float* phase  = (const float*)d_in[5];
    const float* ratio  = (const float*)d_in[6];
    const float* w1 = (const float*)d_in[7];  const float* b1 = (const float*)d_in[8];
    const float* w2 = (const float*)d_in[9];  const float* b2 = (const float*)d_in[10];
    const float* w3 = (const float*)d_in[11]; const float* b3 = (const float*)d_in[12];
    const float* wo = (const float*)d_in[13]; const float* bo = (const float*)d_in[14];
    float* out = (float*)d_out;

    const int T = in_sizes[0] / (BATCH * FEATS);   // 512

    float *hb, *cb, *pb, *d1, *d2, *d3;
    __half *ab, *xb, *p16b;
    unsigned char *mkb;
    cudaGetSymbolAddress((void**)&hb,   g_h);
    cudaGetSymbolAddress((void**)&cb,   g_c);
    cudaGetSymbolAddress((void**)&pb,   g_p);
    cudaGetSymbolAddress((void**)&d1,   g_d1);
    cudaGetSymbolAddress((void**)&d2,   g_d2);
    cudaGetSymbolAddress((void**)&d3,   g_d3);
    cudaGetSymbolAddress((void**)&ab,   g_A);
    cudaGetSymbolAddress((void**)&xb,   g_x16);
    cudaGetSymbolAddress((void**)&p16b, g_p16);
    cudaGetSymbolAddress((void**)&mkb,  g_mask);

    cudaFuncSetAttribute(step_mma, cudaFuncAttributeMaxDynamicSharedMemorySize, SMEM_DYN);

    init_zero<<<512, 256>>>();
    prep_B<<<4096, 256>>>(rec, kernel, bias);
    prep_X<<<4096, 256>>>(x, T);
    prep_mask<<<512, 256>>>(x, T);

    const dim3 sgrid(BATCH / 64, WCOLS / 128);   // (4, 32)
    const int SU = BATCH * UNITS;
    int par = 0;

    // warm phase: T masked steps (per-launch — known-good structure)
    for (int t = 0; t < T; t++) {
        step_mma<<<sgrid, 256, SMEM_DYN>>>(
            ab + par * SU,
            xb + t * BATCH * 64,
            x + t * FEATS, T * FEATS, mkb + t * BATCH,
            hb + par * SU, cb + par * SU,
            hb + (par ^ 1) * SU, cb + (par ^ 1) * SU,
            ab + (par ^ 1) * SU,
            period, phase, ratio);
        par ^= 1;
    }

    // dense stack: h -> d1 -> d2 -> d3 -> (p, out[:,s,:], p fp16)
    auto dense_stack = [&](int s) {
        const float* h = hb + par * SU;
        dense_kernel<<<dim3(16,16), dim3(16,16)>>>(h,  UNITS, w1, 256, b1, d1, 1, nullptr, 0, nullptr);
        dense_kernel<<<dim3(16, 8), dim3(16,16)>>>(d1, 256,   w2, 128, b2, d2, 1, nullptr, 0, nullptr);
        dense_kernel<<<dim3(16, 4), dim3(16,16)>>>(d2, 128,   w3, 64,  b3, d3, 1, nullptr, 0, nullptr);
        dense_kernel<<<dim3(16, 1), dim3(16,16)>>>(d3, 64,    wo, FEATS, bo, pb, 0,
                                                   out + s * FEATS, OUTSTEPS * FEATS, p16b);
    };

    dense_stack(0);   // pred0

    // autoregressive phase: 23 unmasked steps fed by p
    for (int s = 1; s < OUTSTEPS; s++) {
        step_mma<<<sgrid, 256, SMEM_DYN>>>(
            ab + par * SU,
            p16b,
            pb, FEATS, nullptr,
            hb + par * SU, cb + par * SU,
            hb + (par ^ 1) * SU, cb + (par ^ 1) * SU,
            ab + (par ^ 1) * SU,
            period, phase, ratio);
        par ^= 1;
        dense_stack(s);
    }
}